// round 2
// baseline (speedup 1.0000x reference)
#include <cuda_runtime.h>
#include <cuda_bf16.h>
#include <math.h>

// Problem constants: B=2, S=4096, HID=2048, H=16, KV=4, D=128, BS=64, L=4, G=4,
// STRIDE=4, WTOK=2048 (max_away = 32 blocks), nb = 64 blocks.
#define NEGV (-1000000000.0f)
#define SCALEV 0.08838834764831845f   // 1/sqrt(128)

// Scratch (allocation-free rule: __device__ globals)
__device__ float g_Q[2 * 4096 * 2048];   // [B*S, H*D]  (after rope)
__device__ float g_K[2 * 4096 * 512];    // [B*S, KV*D] (after rope)
__device__ float g_V[2 * 4096 * 512];    // [B*S, KV*D]
__device__ float g_AO[2 * 4096 * 2048];  // attention out [B*S, H*D]

// ---------------------------------------------------------------------------
// Classic 128x128 SGEMM, BK=8, 8x8 per thread, 256 threads.
// A [M,K] row-major, B [K,N] row-major, C [M,N] row-major.
// Assumes M%128==0, N%128==0, K%8==0 (true for all four calls).
// ---------------------------------------------------------------------------
__global__ __launch_bounds__(256) void sgemm128(
    const float* __restrict__ A, const float* __restrict__ B, float* __restrict__ C,
    int M, int N, int K)
{
    __shared__ float As[8][128];
    __shared__ float Bs[8][128];
    const int tid = threadIdx.x;
    const int crow0 = blockIdx.y * 128;
    const int ccol0 = blockIdx.x * 128;
    const int aRow = tid >> 1;           // 0..127
    const int aCol = (tid & 1) * 4;      // 0 or 4
    const int bRow = tid >> 5;           // 0..7
    const int bCol = (tid & 31) * 4;     // 0..124
    const int ty = tid >> 4;             // 0..15
    const int tx = tid & 15;             // 0..15

    const float* Ap = A + (size_t)(crow0 + aRow) * K + aCol;
    const float* Bp = B + (size_t)bRow * N + ccol0 + bCol;

    float acc[8][8];
#pragma unroll
    for (int i = 0; i < 8; i++)
#pragma unroll
        for (int j = 0; j < 8; j++) acc[i][j] = 0.f;

    for (int k0 = 0; k0 < K; k0 += 8) {
        float4 a4 = *(const float4*)Ap;
        As[aCol + 0][aRow] = a4.x;
        As[aCol + 1][aRow] = a4.y;
        As[aCol + 2][aRow] = a4.z;
        As[aCol + 3][aRow] = a4.w;
        *(float4*)(&Bs[bRow][bCol]) = *(const float4*)Bp;
        __syncthreads();
#pragma unroll
        for (int kk = 0; kk < 8; kk++) {
            float ar[8], br[8];
            *(float4*)(ar)     = *(const float4*)(&As[kk][ty * 8]);
            *(float4*)(ar + 4) = *(const float4*)(&As[kk][ty * 8 + 4]);
            *(float4*)(br)     = *(const float4*)(&Bs[kk][tx * 8]);
            *(float4*)(br + 4) = *(const float4*)(&Bs[kk][tx * 8 + 4]);
#pragma unroll
            for (int i = 0; i < 8; i++)
#pragma unroll
                for (int j = 0; j < 8; j++)
                    acc[i][j] += ar[i] * br[j];
        }
        __syncthreads();
        Ap += 8;
        Bp += (size_t)8 * N;
    }
#pragma unroll
    for (int i = 0; i < 8; i++) {
        float* Cp = C + (size_t)(crow0 + ty * 8 + i) * N + ccol0 + tx * 8;
        *(float4*)(Cp)     = make_float4(acc[i][0], acc[i][1], acc[i][2], acc[i][3]);
        *(float4*)(Cp + 4) = make_float4(acc[i][4], acc[i][5], acc[i][6], acc[i][7]);
    }
}

// ---------------------------------------------------------------------------
// RoPE in-place: X [B*S, nh*128], cos/sin [B*S, 128].
// blockDim = (64, nh), grid = B*S. Thread d handles the (d, d+64) pair.
// ---------------------------------------------------------------------------
__global__ void rope_kernel(float* __restrict__ X, const float* __restrict__ cosp,
                            const float* __restrict__ sinp, int nh)
{
    const int row = blockIdx.x;
    const int h = threadIdx.y;
    const int d = threadIdx.x; // 0..63
    const float c1 = cosp[row * 128 + d];
    const float s1 = sinp[row * 128 + d];
    const float c2 = cosp[row * 128 + d + 64];
    const float s2 = sinp[row * 128 + d + 64];
    float* xp = X + (size_t)row * (nh * 128) + h * 128;
    const float x1 = xp[d], x2 = xp[d + 64];
    xp[d]      = x1 * c1 - x2 * s1;   // q*cos + (-x2)*sin
    xp[d + 64] = x2 * c2 + x1 * s2;   // q*cos + ( x1)*sin
}

// ---------------------------------------------------------------------------
// Block-sparse attention. One CTA per (qblock, head, batch). 256 threads.
// Smem: Qst [128][65] transposed, Kst [128][65] transposed (aliased by
// Vs [64][128] in phase 3), Ps [64][513] scores, rinv[64].
// ---------------------------------------------------------------------------
#define ATTN_SMEM_FLOATS (8320 * 2 + 64 * 513 + 64)
#define ATTN_SMEM_BYTES  (ATTN_SMEM_FLOATS * 4)

__global__ __launch_bounds__(256) void attn_kernel(
    const float* __restrict__ Q, const float* __restrict__ K, const float* __restrict__ V,
    const float* __restrict__ mask, float* __restrict__ AO)
{
    extern __shared__ float sm[];
    float* Qst  = sm;                  // [128][65]
    float* Kst  = sm + 8320;           // [128][65]
    float* Vs   = Kst;                 // [64][128] (aliases Kst, used after phase 1)
    float* Ps   = sm + 16640;          // [64][513]
    float* rinv = Ps + 64 * 513;       // [64]

    const int qb = blockIdx.x;         // 0..63
    const int h  = blockIdx.y;         // 0..15
    const int b  = blockIdx.z;         // 0..1
    const int kvh = h >> 2;            // H/KV = 4
    const int tid = threadIdx.x;
    const int ty = tid >> 4;           // 0..15
    const int tx = tid & 15;           // 0..15

    // --- key-block table: 4 local (window w=0..3, self = slot 3) + 4 global ---
    int kblk[8]; bool kvalid[8];
#pragma unroll
    for (int w = 0; w < 4; w++) {
        int jb = qb - 3 + w;
        kblk[w] = jb < 0 ? 0 : jb;
        kvalid[w] = (jb >= 0);
    }
    {
        int start = qb - 32; if (start < 0) start = 0;             // max_away = 32
        int cnt = (qb > start) ? ((qb - start + 3) >> 2) : 0;      // ceil((qb-start)/4)
        int first = (cnt > 4) ? (cnt - 4) : 0;                     // keep last 4
        int sz = (cnt < 4) ? cnt : 4;
        int s0 = 4 - sz;                                           // right-align
#pragma unroll
        for (int g = 0; g < 4; g++) {
            if (g < s0) { kblk[4 + g] = 0; kvalid[4 + g] = false; }
            else        { kblk[4 + g] = start + 4 * (first + g - s0); kvalid[4 + g] = true; }
        }
    }

    // --- load Q block transposed: Qst[d][tok] ---
    const float* Qsrc = Q + ((size_t)(b * 4096 + qb * 64)) * 2048 + h * 128;
#pragma unroll
    for (int it = 0; it < 8; it++) {
        int g = tid + it * 256;
        int tok = g >> 5, d4 = g & 31;
        float4 v = *(const float4*)(Qsrc + (size_t)tok * 2048 + d4 * 4);
        Qst[(4 * d4 + 0) * 65 + tok] = v.x;
        Qst[(4 * d4 + 1) * 65 + tok] = v.y;
        Qst[(4 * d4 + 2) * 65 + tok] = v.z;
        Qst[(4 * d4 + 3) * 65 + tok] = v.w;
    }
    // (sync happens inside first valid slot before any Qst read)

    // --- phase 1: scores for all 8 key blocks ---
    for (int slot = 0; slot < 8; slot++) {
        if (kvalid[slot]) {
            const float* Ksrc = K + ((size_t)(b * 4096 + kblk[slot] * 64)) * 512 + kvh * 128;
            __syncthreads();   // prior-iter Kst reads done; also orders Qst stores (1st iter)
#pragma unroll
            for (int it = 0; it < 8; it++) {
                int g = tid + it * 256;
                int tok = g >> 5, d4 = g & 31;
                float4 v = *(const float4*)(Ksrc + (size_t)tok * 512 + d4 * 4);
                Kst[(4 * d4 + 0) * 65 + tok] = v.x;
                Kst[(4 * d4 + 1) * 65 + tok] = v.y;
                Kst[(4 * d4 + 2) * 65 + tok] = v.z;
                Kst[(4 * d4 + 3) * 65 + tok] = v.w;
            }
            __syncthreads();

            float acc[4][4];
#pragma unroll
            for (int i = 0; i < 4; i++)
#pragma unroll
                for (int j = 0; j < 4; j++) acc[i][j] = 0.f;

#pragma unroll 8
            for (int kk = 0; kk < 128; kk++) {
                float a0 = Qst[kk * 65 + ty];
                float a1 = Qst[kk * 65 + ty + 16];
                float a2 = Qst[kk * 65 + ty + 32];
                float a3 = Qst[kk * 65 + ty + 48];
                float b0 = Kst[kk * 65 + tx];
                float b1 = Kst[kk * 65 + tx + 16];
                float b2 = Kst[kk * 65 + tx + 32];
                float b3 = Kst[kk * 65 + tx + 48];
                acc[0][0] += a0 * b0; acc[0][1] += a0 * b1; acc[0][2] += a0 * b2; acc[0][3] += a0 * b3;
                acc[1][0] += a1 * b0; acc[1][1] += a1 * b1; acc[1][2] += a1 * b2; acc[1][3] += a1 * b3;
                acc[2][0] += a2 * b0; acc[2][1] += a2 * b1; acc[2][2] += a2 * b2; acc[2][3] += a2 * b3;
                acc[3][0] += a3 * b0; acc[3][1] += a3 * b1; acc[3][2] += a3 * b2; acc[3][3] += a3 * b3;
            }

            const float* mrow = mask + (size_t)b * 4096 + kblk[slot] * 64;
            const bool cz = (slot == 3);   // self block: causal within
#pragma unroll
            for (int i = 0; i < 4; i++) {
                int r = ty + 16 * i;
#pragma unroll
                for (int j = 0; j < 4; j++) {
                    int c = tx + 16 * j;
                    float sc = acc[i][j] * SCALEV;
                    sc += (1.0f - mrow[c]) * NEGV;
                    if (cz && c > r) sc += NEGV;
                    Ps[r * 513 + slot * 64 + c] = sc;
                }
            }
        } else {
#pragma unroll
            for (int i = 0; i < 4; i++)
#pragma unroll
                for (int j = 0; j < 4; j++)
                    Ps[(ty + 16 * i) * 513 + slot * 64 + tx + 16 * j] = NEGV;
        }
    }
    __syncthreads();

    // --- phase 2: softmax (store unnormalized exp + reciprocal row sums) ---
    if (tid < 64) {
        float* pr = Ps + tid * 513;
        float m = -3.4e38f;
        for (int c = 0; c < 512; c++) m = fmaxf(m, pr[c]);
        float s = 0.f;
        for (int c = 0; c < 512; c++) {
            float e = __expf(pr[c] - m);
            pr[c] = e;
            s += e;
        }
        rinv[tid] = 1.0f / s;
    }
    __syncthreads();

    // --- phase 3: O = P @ V ---
    float o[4][8];
#pragma unroll
    for (int i = 0; i < 4; i++)
#pragma unroll
        for (int j = 0; j < 8; j++) o[i][j] = 0.f;

    for (int slot = 0; slot < 8; slot++) {
        if (!kvalid[slot]) continue;   // exp(NEG - m) == 0, skipping is exact
        const float* Vsrc = V + ((size_t)(b * 4096 + kblk[slot] * 64)) * 512 + kvh * 128;
#pragma unroll
        for (int it = 0; it < 8; it++) {
            int g = tid + it * 256;
            int tok = g >> 5, d4 = g & 31;
            *(float4*)(&Vs[tok * 128 + d4 * 4]) = *(const float4*)(Vsrc + (size_t)tok * 512 + d4 * 4);
        }
        __syncthreads();
#pragma unroll 4
        for (int kk = 0; kk < 64; kk++) {
            float p0 = Ps[(ty     ) * 513 + slot * 64 + kk];
            float p1 = Ps[(ty + 16) * 513 + slot * 64 + kk];
            float p2 = Ps[(ty + 32) * 513 + slot * 64 + kk];
            float p3 = Ps[(ty + 48) * 513 + slot * 64 + kk];
#pragma unroll
            for (int j = 0; j < 8; j++) {
                float v = Vs[kk * 128 + tx + 16 * j];
                o[0][j] += p0 * v;
                o[1][j] += p1 * v;
                o[2][j] += p2 * v;
                o[3][j] += p3 * v;
            }
        }
        __syncthreads();
    }

    // --- epilogue: normalize + write ---
    float* aop = AO + ((size_t)(b * 4096 + qb * 64)) * 2048 + h * 128;
#pragma unroll
    for (int i = 0; i < 4; i++) {
        int r = ty + 16 * i;
        float rs = rinv[r];
#pragma unroll
        for (int j = 0; j < 8; j++)
            aop[(size_t)r * 2048 + tx + 16 * j] = o[i][j] * rs;
    }
}

// ---------------------------------------------------------------------------
// kernel_launch: graph-capturable, allocation-free.
// Inputs: hidden, cos, sin, attention_mask_2d, Wq, Wk, Wv, Wo. Output fp32.
// ---------------------------------------------------------------------------
extern "C" void kernel_launch(void* const* d_in, const int* in_sizes, int n_in,
                              void* d_out, int out_size)
{
    const float* hidden = (const float*)d_in[0];
    const float* cosp   = (const float*)d_in[1];
    const float* sinp   = (const float*)d_in[2];
    const float* maskp  = (const float*)d_in[3];
    const float* Wq     = (const float*)d_in[4];
    const float* Wk     = (const float*)d_in[5];
    const float* Wv     = (const float*)d_in[6];
    const float* Wo     = (const float*)d_in[7];
    float* out = (float*)d_out;

    float *Qp, *Kp, *Vp, *AOp;
    cudaGetSymbolAddress((void**)&Qp, g_Q);
    cudaGetSymbolAddress((void**)&Kp, g_K);
    cudaGetSymbolAddress((void**)&Vp, g_V);
    cudaGetSymbolAddress((void**)&AOp, g_AO);

    cudaFuncSetAttribute(attn_kernel, cudaFuncAttributeMaxDynamicSharedMemorySize,
                         ATTN_SMEM_BYTES);

    // projections
    sgemm128<<<dim3(16, 64), 256>>>(hidden, Wq, Qp, 8192, 2048, 2048);
    sgemm128<<<dim3(4, 64), 256>>>(hidden, Wk, Kp, 8192, 512, 2048);
    sgemm128<<<dim3(4, 64), 256>>>(hidden, Wv, Vp, 8192, 512, 2048);
    // rope (Q: 16 heads, K: 4 heads)
    rope_kernel<<<8192, dim3(64, 16)>>>(Qp, cosp, sinp, 16);
    rope_kernel<<<8192, dim3(64, 4)>>>(Kp, cosp, sinp, 4);
    // block-sparse attention
    attn_kernel<<<dim3(64, 16, 2), 256, ATTN_SMEM_BYTES>>>(Qp, Kp, Vp, maskp, AOp);
    // output projection
    sgemm128<<<dim3(16, 64), 256>>>(AOp, Wo, out, 8192, 2048, 2048);
}

// round 5
// speedup vs baseline: 2.3366x; 2.3366x over previous
#include <cuda_runtime.h>
#include <cuda_bf16.h>
#include <math.h>
#include <stdint.h>

// B=2, S=4096, HID=2048, H=16, KV=4, D=128, BS=64, L=4, G=4, STRIDE=4, WTOK=2048
#define NEGV (-1000000000.0f)
#define SCALEV 0.08838834764831845f   // 1/sqrt(128)

// ---------------- scratch (__device__ globals; allocation-free rule) -------
__device__ __align__(1024) float g_Q  [2 * 4096 * 2048];
__device__ __align__(1024) float g_K  [2 * 4096 * 512];
__device__ __align__(1024) float g_V  [2 * 4096 * 512];
__device__ __align__(1024) float g_AO [2 * 4096 * 2048];
__device__ __align__(1024) float g_Xr [2 * 4096 * 2048];  // rna-rounded hidden
__device__ __align__(1024) float g_WqT[2048 * 2048];
__device__ __align__(1024) float g_WkT[512 * 2048];
__device__ __align__(1024) float g_WvT[512 * 2048];
__device__ __align__(1024) float g_WoT[2048 * 2048];

// ---------------- helpers ---------------------------------------------------
__device__ __forceinline__ uint32_t smem_u32(const void* p) {
    uint32_t a;
    asm("{ .reg .u64 t; cvta.to.shared.u64 t, %1; cvt.u32.u64 %0, t; }" : "=r"(a) : "l"(p));
    return a;
}
__device__ __forceinline__ float rna_tf32(float x) {
    uint32_t u;
    asm("cvt.rna.tf32.f32 %0, %1;" : "=r"(u) : "f"(x));
    return __uint_as_float(u);
}
#define CP_ASYNC16(sm, gm) \
    asm volatile("cp.async.cg.shared.global [%0], [%1], 16;" :: "r"(sm), "l"(gm) : "memory")
#define CP_COMMIT() asm volatile("cp.async.commit_group;" ::: "memory")
#define CP_WAIT0()  asm volatile("cp.async.wait_group 0;" ::: "memory")
#define CP_WAIT1()  asm volatile("cp.async.wait_group 1;" ::: "memory")

__device__ __forceinline__ void mma_tf32(float c[4], const uint32_t a[4], const uint32_t b[2]) {
    asm volatile(
        "mma.sync.aligned.m16n8k8.row.col.f32.tf32.tf32.f32 "
        "{%0,%1,%2,%3}, {%4,%5,%6,%7}, {%8,%9}, {%0,%1,%2,%3};"
        : "+f"(c[0]), "+f"(c[1]), "+f"(c[2]), "+f"(c[3])
        : "r"(a[0]), "r"(a[1]), "r"(a[2]), "r"(a[3]), "r"(b[0]), "r"(b[1]));
}

// ---------------------------------------------------------------------------
// HMMA tf32 GEMM: C[M,N] = A[M,K] * Bt[N,K]^T (row-major; A,Bt tf32-rounded).
// 128x128x32 CTA tile, 256 threads, warp tile 64x32, cp.async double buffer.
// ---------------------------------------------------------------------------
#define GKSTRIDE 36
#define GSM_FLOATS (2 * 128 * GKSTRIDE * 2)           // A + B, 2 stages
#define GSM_BYTES  (GSM_FLOATS * 4)                   // 73728

__global__ __launch_bounds__(256, 2) void gemm_mma(
    const float* __restrict__ A, const float* __restrict__ Bt, float* __restrict__ C,
    int M, int N, int K)
{
    extern __shared__ float sm[];
    float* As = sm;                       // [2][128][36]
    float* Bs = sm + 2 * 128 * GKSTRIDE;  // [2][128][36]
    const uint32_t smbA = smem_u32(As);
    const uint32_t smbB = smem_u32(Bs);

    const int tid  = threadIdx.x;
    const int lane = tid & 31;
    const int warp = tid >> 5;
    const int wm = warp & 1;              // 0..1  (64-row half)
    const int wn = warp >> 1;             // 0..3  (32-col quarter)
    const int lr = lane >> 2;             // 0..7
    const int lc = lane & 3;              // 0..3
    const int crow0 = blockIdx.y * 128;
    const int ccol0 = blockIdx.x * 128;

    const int ldrow = tid >> 3;           // 0..31 base row for cp.async
    const int ldc4  = tid & 7;            // 16B chunk in a 32-float row

    float acc[4][4][4];
#pragma unroll
    for (int mt = 0; mt < 4; mt++)
#pragma unroll
        for (int nt = 0; nt < 4; nt++)
#pragma unroll
            for (int i = 0; i < 4; i++) acc[mt][nt][i] = 0.f;

    const int T = K >> 5;   // stages of BK=32

    // stage loader: 4 A-chunks + 4 B-chunks of 16B per thread
#define GLOAD(buf, k0)                                                               \
    do {                                                                             \
        _Pragma("unroll")                                                            \
        for (int it = 0; it < 4; it++) {                                             \
            const int row = ldrow + it * 32;                                         \
            const uint32_t so = (uint32_t)(((buf) * 128 + row) * GKSTRIDE + ldc4 * 4) * 4; \
            CP_ASYNC16(smbA + so, A  + (size_t)(crow0 + row) * K + (k0) + ldc4 * 4); \
            CP_ASYNC16(smbB + so, Bt + (size_t)(ccol0 + row) * K + (k0) + ldc4 * 4); \
        }                                                                            \
    } while (0)

    GLOAD(0, 0);
    CP_COMMIT();

    for (int t = 0; t < T; t++) {
        const int buf = t & 1;
        if (t + 1 < T) {
            GLOAD(buf ^ 1, (t + 1) << 5);
            CP_COMMIT();
            CP_WAIT1();
        } else {
            CP_WAIT0();
        }
        __syncthreads();

        const float* Ab = As + buf * 128 * GKSTRIDE;
        const float* Bb = Bs + buf * 128 * GKSTRIDE;
#pragma unroll
        for (int kk = 0; kk < 4; kk++) {
            const int col = kk * 8 + lc;
            uint32_t af[4][4];
#pragma unroll
            for (int mt = 0; mt < 4; mt++) {
                const float* p = Ab + (wm * 64 + mt * 16 + lr) * GKSTRIDE + col;
                af[mt][0] = __float_as_uint(p[0]);
                af[mt][1] = __float_as_uint(p[8 * GKSTRIDE]);
                af[mt][2] = __float_as_uint(p[4]);
                af[mt][3] = __float_as_uint(p[8 * GKSTRIDE + 4]);
            }
            uint32_t bf[4][2];
#pragma unroll
            for (int nt = 0; nt < 4; nt++) {
                const float* p = Bb + (wn * 32 + nt * 8 + lr) * GKSTRIDE + col;
                bf[nt][0] = __float_as_uint(p[0]);
                bf[nt][1] = __float_as_uint(p[4]);
            }
#pragma unroll
            for (int mt = 0; mt < 4; mt++)
#pragma unroll
                for (int nt = 0; nt < 4; nt++)
                    mma_tf32(acc[mt][nt], af[mt], bf[nt]);
        }
        __syncthreads();
    }

    // epilogue: direct float2 stores
#pragma unroll
    for (int mt = 0; mt < 4; mt++) {
        const int row = crow0 + wm * 64 + mt * 16 + lr;
#pragma unroll
        for (int nt = 0; nt < 4; nt++) {
            const int col = ccol0 + wn * 32 + nt * 8 + 2 * lc;
            *(float2*)(C + (size_t)row * N + col)       = make_float2(acc[mt][nt][0], acc[mt][nt][1]);
            *(float2*)(C + (size_t)(row + 8) * N + col) = make_float2(acc[mt][nt][2], acc[mt][nt][3]);
        }
    }
}

// ---------------------------------------------------------------------------
// prep kernels
// ---------------------------------------------------------------------------
__global__ void round_copy(const float* __restrict__ src, float* __restrict__ dst, int n4) {
    int i = blockIdx.x * blockDim.x + threadIdx.x;
    if (i < n4) {
        float4 v = ((const float4*)src)[i];
        v.x = rna_tf32(v.x); v.y = rna_tf32(v.y); v.z = rna_tf32(v.z); v.w = rna_tf32(v.w);
        ((float4*)dst)[i] = v;
    }
}
// W [K,N] -> Wt [N,K], rna-rounded. blockDim (32,8), grid (N/32, K/32).
__global__ void transpose_round(const float* __restrict__ W, float* __restrict__ Wt,
                                int K, int N) {
    __shared__ float t[32][33];
    const int n0 = blockIdx.x * 32, k0 = blockIdx.y * 32;
    const int x = threadIdx.x, y = threadIdx.y;
#pragma unroll
    for (int j = 0; j < 32; j += 8)
        t[y + j][x] = W[(size_t)(k0 + y + j) * N + n0 + x];
    __syncthreads();
#pragma unroll
    for (int j = 0; j < 32; j += 8)
        Wt[(size_t)(n0 + y + j) * K + k0 + x] = rna_tf32(t[x][y + j]);
}

// ---------------------------------------------------------------------------
// RoPE in-place: X [B*S, nh*128], cos/sin [B*S, 128]
// ---------------------------------------------------------------------------
__global__ void rope_kernel(float* __restrict__ X, const float* __restrict__ cosp,
                            const float* __restrict__ sinp, int nh)
{
    const int row = blockIdx.x;
    const int h = threadIdx.y;
    const int d = threadIdx.x;
    const float c1 = cosp[row * 128 + d];
    const float s1 = sinp[row * 128 + d];
    const float c2 = cosp[row * 128 + d + 64];
    const float s2 = sinp[row * 128 + d + 64];
    float* xp = X + (size_t)row * (nh * 128) + h * 128;
    const float x1 = xp[d], x2 = xp[d + 64];
    xp[d]      = x1 * c1 - x2 * s1;
    xp[d + 64] = x2 * c2 + x1 * s2;
}

// ---------------------------------------------------------------------------
// Block-sparse attention (fp32). One CTA per (qblock, head, batch). 256 thr.
// Writes AO rna-rounded (feeds the tf32 Wo GEMM).
// ---------------------------------------------------------------------------
#define ATTN_SMEM_FLOATS (8320 * 2 + 64 * 513 + 64)
#define ATTN_SMEM_BYTES  (ATTN_SMEM_FLOATS * 4)

__global__ __launch_bounds__(256) void attn_kernel(
    const float* __restrict__ Q, const float* __restrict__ K, const float* __restrict__ V,
    const float* __restrict__ mask, float* __restrict__ AO)
{
    extern __shared__ float smf[];
    float* Qst  = smf;                  // [128][65]
    float* Kst  = smf + 8320;           // [128][65]
    float* Vs   = Kst;                  // [64][128] (aliased, used after phase 1)
    float* Ps   = smf + 16640;          // [64][513]
    float* rinv = Ps + 64 * 513;        // [64]

    const int qb = blockIdx.x;
    const int h  = blockIdx.y;
    const int b  = blockIdx.z;
    const int kvh = h >> 2;
    const int tid = threadIdx.x;
    const int ty = tid >> 4;
    const int tx = tid & 15;

    int kblk[8]; bool kvalid[8];
#pragma unroll
    for (int w = 0; w < 4; w++) {
        int jb = qb - 3 + w;
        kblk[w] = jb < 0 ? 0 : jb;
        kvalid[w] = (jb >= 0);
    }
    {
        int start = qb - 32; if (start < 0) start = 0;
        int cnt = (qb > start) ? ((qb - start + 3) >> 2) : 0;
        int first = (cnt > 4) ? (cnt - 4) : 0;
        int sz = (cnt < 4) ? cnt : 4;
        int s0 = 4 - sz;
#pragma unroll
        for (int g = 0; g < 4; g++) {
            if (g < s0) { kblk[4 + g] = 0; kvalid[4 + g] = false; }
            else        { kblk[4 + g] = start + 4 * (first + g - s0); kvalid[4 + g] = true; }
        }
    }

    const float* Qsrc = Q + ((size_t)(b * 4096 + qb * 64)) * 2048 + h * 128;
#pragma unroll
    for (int it = 0; it < 8; it++) {
        int g = tid + it * 256;
        int tok = g >> 5, d4 = g & 31;
        float4 v = *(const float4*)(Qsrc + (size_t)tok * 2048 + d4 * 4);
        Qst[(4 * d4 + 0) * 65 + tok] = v.x;
        Qst[(4 * d4 + 1) * 65 + tok] = v.y;
        Qst[(4 * d4 + 2) * 65 + tok] = v.z;
        Qst[(4 * d4 + 3) * 65 + tok] = v.w;
    }

    for (int slot = 0; slot < 8; slot++) {
        if (kvalid[slot]) {
            const float* Ksrc = K + ((size_t)(b * 4096 + kblk[slot] * 64)) * 512 + kvh * 128;
            __syncthreads();
#pragma unroll
            for (int it = 0; it < 8; it++) {
                int g = tid + it * 256;
                int tok = g >> 5, d4 = g & 31;
                float4 v = *(const float4*)(Ksrc + (size_t)tok * 512 + d4 * 4);
                Kst[(4 * d4 + 0) * 65 + tok] = v.x;
                Kst[(4 * d4 + 1) * 65 + tok] = v.y;
                Kst[(4 * d4 + 2) * 65 + tok] = v.z;
                Kst[(4 * d4 + 3) * 65 + tok] = v.w;
            }
            __syncthreads();

            float acc[4][4];
#pragma unroll
            for (int i = 0; i < 4; i++)
#pragma unroll
                for (int j = 0; j < 4; j++) acc[i][j] = 0.f;

#pragma unroll 8
            for (int kk = 0; kk < 128; kk++) {
                float a0 = Qst[kk * 65 + ty];
                float a1 = Qst[kk * 65 + ty + 16];
                float a2 = Qst[kk * 65 + ty + 32];
                float a3 = Qst[kk * 65 + ty + 48];
                float b0 = Kst[kk * 65 + tx];
                float b1 = Kst[kk * 65 + tx + 16];
                float b2 = Kst[kk * 65 + tx + 32];
                float b3 = Kst[kk * 65 + tx + 48];
                acc[0][0] += a0 * b0; acc[0][1] += a0 * b1; acc[0][2] += a0 * b2; acc[0][3] += a0 * b3;
                acc[1][0] += a1 * b0; acc[1][1] += a1 * b1; acc[1][2] += a1 * b2; acc[1][3] += a1 * b3;
                acc[2][0] += a2 * b0; acc[2][1] += a2 * b1; acc[2][2] += a2 * b2; acc[2][3] += a2 * b3;
                acc[3][0] += a3 * b0; acc[3][1] += a3 * b1; acc[3][2] += a3 * b2; acc[3][3] += a3 * b3;
            }

            const float* mrow = mask + (size_t)b * 4096 + kblk[slot] * 64;
            const bool cz = (slot == 3);
#pragma unroll
            for (int i = 0; i < 4; i++) {
                int r = ty + 16 * i;
#pragma unroll
                for (int j = 0; j < 4; j++) {
                    int c = tx + 16 * j;
                    float sc = acc[i][j] * SCALEV;
                    sc += (1.0f - mrow[c]) * NEGV;
                    if (cz && c > r) sc += NEGV;
                    Ps[r * 513 + slot * 64 + c] = sc;
                }
            }
        } else {
#pragma unroll
            for (int i = 0; i < 4; i++)
#pragma unroll
                for (int j = 0; j < 4; j++)
                    Ps[(ty + 16 * i) * 513 + slot * 64 + tx + 16 * j] = NEGV;
        }
    }
    __syncthreads();

    if (tid < 64) {
        float* pr = Ps + tid * 513;
        float m = -3.4e38f;
        for (int c = 0; c < 512; c++) m = fmaxf(m, pr[c]);
        float s = 0.f;
        for (int c = 0; c < 512; c++) {
            float e = __expf(pr[c] - m);
            pr[c] = e;
            s += e;
        }
        rinv[tid] = 1.0f / s;
    }
    __syncthreads();

    float o[4][8];
#pragma unroll
    for (int i = 0; i < 4; i++)
#pragma unroll
        for (int j = 0; j < 8; j++) o[i][j] = 0.f;

    for (int slot = 0; slot < 8; slot++) {
        if (!kvalid[slot]) continue;
        const float* Vsrc = V + ((size_t)(b * 4096 + kblk[slot] * 64)) * 512 + kvh * 128;
#pragma unroll
        for (int it = 0; it < 8; it++) {
            int g = tid + it * 256;
            int tok = g >> 5, d4 = g & 31;
            *(float4*)(&Vs[tok * 128 + d4 * 4]) = *(const float4*)(Vsrc + (size_t)tok * 512 + d4 * 4);
        }
        __syncthreads();
#pragma unroll 4
        for (int kk = 0; kk < 64; kk++) {
            float p0 = Ps[(ty     ) * 513 + slot * 64 + kk];
            float p1 = Ps[(ty + 16) * 513 + slot * 64 + kk];
            float p2 = Ps[(ty + 32) * 513 + slot * 64 + kk];
            float p3 = Ps[(ty + 48) * 513 + slot * 64 + kk];
#pragma unroll
            for (int j = 0; j < 8; j++) {
                float v = Vs[kk * 128 + tx + 16 * j];
                o[0][j] += p0 * v;
                o[1][j] += p1 * v;
                o[2][j] += p2 * v;
                o[3][j] += p3 * v;
            }
        }
        __syncthreads();
    }

    float* aop = AO + ((size_t)(b * 4096 + qb * 64)) * 2048 + h * 128;
#pragma unroll
    for (int i = 0; i < 4; i++) {
        int r = ty + 16 * i;
        float rs = rinv[r];
#pragma unroll
        for (int j = 0; j < 8; j++)
            aop[(size_t)r * 2048 + tx + 16 * j] = rna_tf32(o[i][j] * rs);
    }
}

// ---------------------------------------------------------------------------
extern "C" void kernel_launch(void* const* d_in, const int* in_sizes, int n_in,
                              void* d_out, int out_size)
{
    const float* hidden = (const float*)d_in[0];
    const float* cosp   = (const float*)d_in[1];
    const float* sinp   = (const float*)d_in[2];
    const float* maskp  = (const float*)d_in[3];
    const float* Wq     = (const float*)d_in[4];
    const float* Wk     = (const float*)d_in[5];
    const float* Wv     = (const float*)d_in[6];
    const float* Wo     = (const float*)d_in[7];
    float* out = (float*)d_out;

    float *Qp, *Kp, *Vp, *AOp, *Xr, *WqT, *WkT, *WvT, *WoT;
    cudaGetSymbolAddress((void**)&Qp, g_Q);
    cudaGetSymbolAddress((void**)&Kp, g_K);
    cudaGetSymbolAddress((void**)&Vp, g_V);
    cudaGetSymbolAddress((void**)&AOp, g_AO);
    cudaGetSymbolAddress((void**)&Xr, g_Xr);
    cudaGetSymbolAddress((void**)&WqT, g_WqT);
    cudaGetSymbolAddress((void**)&WkT, g_WkT);
    cudaGetSymbolAddress((void**)&WvT, g_WvT);
    cudaGetSymbolAddress((void**)&WoT, g_WoT);

    cudaFuncSetAttribute(attn_kernel, cudaFuncAttributeMaxDynamicSharedMemorySize,
                         ATTN_SMEM_BYTES);
    cudaFuncSetAttribute(gemm_mma, cudaFuncAttributeMaxDynamicSharedMemorySize,
                         GSM_BYTES);

    // prep: round hidden, transpose+round weights (tf32 grid)
    const int n4 = 2 * 4096 * 2048 / 4;
    round_copy<<<(n4 + 255) / 256, 256>>>(hidden, Xr, n4);
    transpose_round<<<dim3(2048 / 32, 2048 / 32), dim3(32, 8)>>>(Wq, WqT, 2048, 2048);
    transpose_round<<<dim3(512 / 32, 2048 / 32), dim3(32, 8)>>>(Wk, WkT, 2048, 512);
    transpose_round<<<dim3(512 / 32, 2048 / 32), dim3(32, 8)>>>(Wv, WvT, 2048, 512);
    transpose_round<<<dim3(2048 / 32, 2048 / 32), dim3(32, 8)>>>(Wo, WoT, 2048, 2048);

    // projections (HMMA tf32)
    gemm_mma<<<dim3(16, 64), 256, GSM_BYTES>>>(Xr, WqT, Qp, 8192, 2048, 2048);
    gemm_mma<<<dim3(4, 64), 256, GSM_BYTES>>>(Xr, WkT, Kp, 8192, 512, 2048);
    gemm_mma<<<dim3(4, 64), 256, GSM_BYTES>>>(Xr, WvT, Vp, 8192, 512, 2048);

    // rope
    rope_kernel<<<8192, dim3(64, 16)>>>(Qp, cosp, sinp, 16);
    rope_kernel<<<8192, dim3(64, 4)>>>(Kp, cosp, sinp, 4);

    // block-sparse attention
    attn_kernel<<<dim3(64, 16, 2), 256, ATTN_SMEM_BYTES>>>(Qp, Kp, Vp, maskp, AOp);

    // output projection (HMMA tf32)
    gemm_mma<<<dim3(16, 64), 256, GSM_BYTES>>>(AOp, WoT, out, 8192, 2048, 2048);
}

// round 8
// speedup vs baseline: 3.5386x; 1.5144x over previous
#include <cuda_runtime.h>
#include <cuda_bf16.h>
#include <math.h>
#include <stdint.h>

// B=2, S=4096, HID=2048, H=16, KV=4, D=128, BS=64, L=4, G=4, STRIDE=4, WTOK=2048
#define NEGV (-1000000000.0f)
#define SCALEV 0.08838834764831845f   // 1/sqrt(128)

// ---------------- scratch (__device__ globals; allocation-free rule) -------
__device__ __align__(1024) float g_Q  [2 * 4096 * 2048];
__device__ __align__(1024) float g_K  [2 * 4096 * 512];
__device__ __align__(1024) float g_V  [2 * 4096 * 512];
__device__ __align__(1024) float g_AO [2 * 4096 * 2048];
__device__ __align__(1024) float g_Xr [2 * 4096 * 2048];  // rna-rounded hidden
__device__ __align__(1024) float g_WqT[2048 * 2048];
__device__ __align__(1024) float g_WkT[512 * 2048];
__device__ __align__(1024) float g_WvT[512 * 2048];
__device__ __align__(1024) float g_WoT[2048 * 2048];

// ---------------- helpers ---------------------------------------------------
__device__ __forceinline__ uint32_t smem_u32(const void* p) {
    uint32_t a;
    asm("{ .reg .u64 t; cvta.to.shared.u64 t, %1; cvt.u32.u64 %0, t; }" : "=r"(a) : "l"(p));
    return a;
}
__device__ __forceinline__ float rna_tf32(float x) {
    uint32_t u;
    asm("cvt.rna.tf32.f32 %0, %1;" : "=r"(u) : "f"(x));
    return __uint_as_float(u);
}
#define CP_ASYNC16(sm, gm) \
    asm volatile("cp.async.cg.shared.global [%0], [%1], 16;" :: "r"(sm), "l"(gm) : "memory")
#define CP_COMMIT() asm volatile("cp.async.commit_group;" ::: "memory")
#define CP_WAIT0()  asm volatile("cp.async.wait_group 0;" ::: "memory")
#define CP_WAIT1()  asm volatile("cp.async.wait_group 1;" ::: "memory")

__device__ __forceinline__ void mma_tf32(float c[4], const uint32_t a[4], const uint32_t b[2]) {
    asm volatile(
        "mma.sync.aligned.m16n8k8.row.col.f32.tf32.tf32.f32 "
        "{%0,%1,%2,%3}, {%4,%5,%6,%7}, {%8,%9}, {%0,%1,%2,%3};"
        : "+f"(c[0]), "+f"(c[1]), "+f"(c[2]), "+f"(c[3])
        : "r"(a[0]), "r"(a[1]), "r"(a[2]), "r"(a[3]), "r"(b[0]), "r"(b[1]));
}

// ---------------------------------------------------------------------------
// HMMA tf32 GEMM: C[M,N] = A[M,K] * Bt[N,K]^T (row-major; A,Bt tf32-rounded).
// 128x128x32 CTA tile, 256 threads, warp tile 64x32, cp.async double buffer.
// ---------------------------------------------------------------------------
#define GKSTRIDE 36
#define GSM_FLOATS (2 * 128 * GKSTRIDE * 2)
#define GSM_BYTES  (GSM_FLOATS * 4)

__global__ __launch_bounds__(256, 2) void gemm_mma(
    const float* __restrict__ A, const float* __restrict__ Bt, float* __restrict__ C,
    int M, int N, int K)
{
    extern __shared__ float sm[];
    float* As = sm;
    float* Bs = sm + 2 * 128 * GKSTRIDE;
    const uint32_t smbA = smem_u32(As);
    const uint32_t smbB = smem_u32(Bs);

    const int tid  = threadIdx.x;
    const int lane = tid & 31;
    const int warp = tid >> 5;
    const int wm = warp & 1;
    const int wn = warp >> 1;
    const int lr = lane >> 2;
    const int lc = lane & 3;
    const int crow0 = blockIdx.y * 128;
    const int ccol0 = blockIdx.x * 128;

    const int ldrow = tid >> 3;
    const int ldc4  = tid & 7;

    float acc[4][4][4];
#pragma unroll
    for (int mt = 0; mt < 4; mt++)
#pragma unroll
        for (int nt = 0; nt < 4; nt++)
#pragma unroll
            for (int i = 0; i < 4; i++) acc[mt][nt][i] = 0.f;

    const int T = K >> 5;

#define GLOAD(buf, k0)                                                               \
    do {                                                                             \
        _Pragma("unroll")                                                            \
        for (int it = 0; it < 4; it++) {                                             \
            const int row = ldrow + it * 32;                                         \
            const uint32_t so = (uint32_t)(((buf) * 128 + row) * GKSTRIDE + ldc4 * 4) * 4; \
            CP_ASYNC16(smbA + so, A  + (size_t)(crow0 + row) * K + (k0) + ldc4 * 4); \
            CP_ASYNC16(smbB + so, Bt + (size_t)(ccol0 + row) * K + (k0) + ldc4 * 4); \
        }                                                                            \
    } while (0)

    GLOAD(0, 0);
    CP_COMMIT();

    for (int t = 0; t < T; t++) {
        const int buf = t & 1;
        if (t + 1 < T) {
            GLOAD(buf ^ 1, (t + 1) << 5);
            CP_COMMIT();
            CP_WAIT1();
        } else {
            CP_WAIT0();
        }
        __syncthreads();

        const float* Ab = As + buf * 128 * GKSTRIDE;
        const float* Bb = Bs + buf * 128 * GKSTRIDE;
#pragma unroll
        for (int kk = 0; kk < 4; kk++) {
            const int col = kk * 8 + lc;
            uint32_t af[4][4];
#pragma unroll
            for (int mt = 0; mt < 4; mt++) {
                const float* p = Ab + (wm * 64 + mt * 16 + lr) * GKSTRIDE + col;
                af[mt][0] = __float_as_uint(p[0]);
                af[mt][1] = __float_as_uint(p[8 * GKSTRIDE]);
                af[mt][2] = __float_as_uint(p[4]);
                af[mt][3] = __float_as_uint(p[8 * GKSTRIDE + 4]);
            }
            uint32_t bf[4][2];
#pragma unroll
            for (int nt = 0; nt < 4; nt++) {
                const float* p = Bb + (wn * 32 + nt * 8 + lr) * GKSTRIDE + col;
                bf[nt][0] = __float_as_uint(p[0]);
                bf[nt][1] = __float_as_uint(p[4]);
            }
#pragma unroll
            for (int mt = 0; mt < 4; mt++)
#pragma unroll
                for (int nt = 0; nt < 4; nt++)
                    mma_tf32(acc[mt][nt], af[mt], bf[nt]);
        }
        __syncthreads();
    }

#pragma unroll
    for (int mt = 0; mt < 4; mt++) {
        const int row = crow0 + wm * 64 + mt * 16 + lr;
#pragma unroll
        for (int nt = 0; nt < 4; nt++) {
            const int col = ccol0 + wn * 32 + nt * 8 + 2 * lc;
            *(float2*)(C + (size_t)row * N + col)       = make_float2(acc[mt][nt][0], acc[mt][nt][1]);
            *(float2*)(C + (size_t)(row + 8) * N + col) = make_float2(acc[mt][nt][2], acc[mt][nt][3]);
        }
    }
}

// ---------------------------------------------------------------------------
// prep kernels
// ---------------------------------------------------------------------------
__global__ void round_copy(const float* __restrict__ src, float* __restrict__ dst, int n4) {
    int i = blockIdx.x * blockDim.x + threadIdx.x;
    if (i < n4) {
        float4 v = ((const float4*)src)[i];
        v.x = rna_tf32(v.x); v.y = rna_tf32(v.y); v.z = rna_tf32(v.z); v.w = rna_tf32(v.w);
        ((float4*)dst)[i] = v;
    }
}
__global__ void transpose_round(const float* __restrict__ W, float* __restrict__ Wt,
                                int K, int N) {
    __shared__ float t[32][33];
    const int n0 = blockIdx.x * 32, k0 = blockIdx.y * 32;
    const int x = threadIdx.x, y = threadIdx.y;
#pragma unroll
    for (int j = 0; j < 32; j += 8)
        t[y + j][x] = W[(size_t)(k0 + y + j) * N + n0 + x];
    __syncthreads();
#pragma unroll
    for (int j = 0; j < 32; j += 8)
        Wt[(size_t)(n0 + y + j) * K + k0 + x] = rna_tf32(t[x][y + j]);
}

// ---------------------------------------------------------------------------
// RoPE in-place, writes rna-rounded (Q/K feed the tf32 attention MMAs).
// ---------------------------------------------------------------------------
__global__ void rope_kernel(float* __restrict__ X, const float* __restrict__ cosp,
                            const float* __restrict__ sinp, int nh)
{
    const int row = blockIdx.x;
    const int h = threadIdx.y;
    const int d = threadIdx.x;
    const float c1 = cosp[row * 128 + d];
    const float s1 = sinp[row * 128 + d];
    const float c2 = cosp[row * 128 + d + 64];
    const float s2 = sinp[row * 128 + d + 64];
    float* xp = X + (size_t)row * (nh * 128) + h * 128;
    const float x1 = xp[d], x2 = xp[d + 64];
    xp[d]      = rna_tf32(x1 * c1 - x2 * s1);
    xp[d + 64] = rna_tf32(x2 * c2 + x1 * s2);
}

// ---------------------------------------------------------------------------
// Tensor-core block-sparse attention. One CTA per (qblock, head, batch).
// 256 threads / 8 warps, mma.m16n8k8.tf32 for QK^T and PV.
// smem (floats): Ps[64][516] | Qs[64][132] | KVs (64x132 K / 64x136 V) | rinv[64]
// All fragment LDS patterns conflict-free (strides 516/132/136).
// ---------------------------------------------------------------------------
#define APS  0
#define AQS  (64 * 516)                 // 33024
#define AKV  (AQS + 64 * 132)           // 41472
#define ARI  (AKV + 64 * 136)           // 50176
#define ATTN_SMEM_FLOATS (ARI + 64)     // 50240
#define ATTN_SMEM_BYTES  (ATTN_SMEM_FLOATS * 4)   // 200960

__global__ __launch_bounds__(256, 1) void attn_mma(
    const float* __restrict__ Q, const float* __restrict__ K, const float* __restrict__ V,
    const float* __restrict__ mask, float* __restrict__ AO)
{
    extern __shared__ float smf[];
    float* Ps   = smf + APS;
    float* Qs   = smf + AQS;
    float* KVs  = smf + AKV;
    float* rinv = smf + ARI;

    const int qb = blockIdx.x;
    const int h  = blockIdx.y;
    const int b  = blockIdx.z;
    const int kvh = h >> 2;
    const int tid = threadIdx.x;
    const int lane = tid & 31;
    const int warp = tid >> 5;
    const int lr = lane >> 2;       // 0..7
    const int lc = lane & 3;        // 0..3

    // --- key-block table: 4 local (self = slot 3) + 4 strided global ---
    int kblk[8]; bool kvalid[8];
#pragma unroll
    for (int w = 0; w < 4; w++) {
        int jb = qb - 3 + w;
        kblk[w] = jb < 0 ? 0 : jb;
        kvalid[w] = (jb >= 0);
    }
    {
        int start = qb - 32; if (start < 0) start = 0;
        int cnt = (qb > start) ? ((qb - start + 3) >> 2) : 0;
        int first = (cnt > 4) ? (cnt - 4) : 0;
        int sz = (cnt < 4) ? cnt : 4;
        int s0 = 4 - sz;
#pragma unroll
        for (int g = 0; g < 4; g++) {
            if (g < s0) { kblk[4 + g] = 0; kvalid[4 + g] = false; }
            else        { kblk[4 + g] = start + 4 * (first + g - s0); kvalid[4 + g] = true; }
        }
    }

    // --- load Q (64x128, stride 132) + prefetch K slot 0 into regs ---
    float4 kreg[8];
    {
        const float* Qsrc = Q + (size_t)(b * 4096 + qb * 64) * 2048 + h * 128;
#pragma unroll
        for (int it = 0; it < 8; it++) {
            int f = tid + it * 256;
            int tok = f >> 5, d4 = f & 31;
            *(float4*)(Qs + tok * 132 + d4 * 4) =
                *(const float4*)(Qsrc + (size_t)tok * 2048 + d4 * 4);
        }
        const float* Ksrc = K + (size_t)(b * 4096 + kblk[0] * 64) * 512 + kvh * 128;
#pragma unroll
        for (int it = 0; it < 8; it++) {
            int f = tid + it * 256;
            kreg[it] = *(const float4*)(Ksrc + (size_t)(f >> 5) * 512 + (f & 31) * 4);
        }
    }
    __syncthreads();

    // ================= Phase A: S = Q K^T, per slot =================
    const int wm16 = (warp >> 1) * 16;   // row base (4 groups)
    const int wn32 = (warp & 1) * 32;    // col base (2 groups)

    for (int s = 0; s < 8; s++) {
        // stage K slot s (regs -> smem, stride 132)
#pragma unroll
        for (int it = 0; it < 8; it++) {
            int f = tid + it * 256;
            *(float4*)(KVs + (f >> 5) * 132 + (f & 31) * 4) = kreg[it];
        }
        __syncthreads();
        // prefetch next K (or V slot 0 at the end)
        {
            const float* src = (s < 7)
                ? K + (size_t)(b * 4096 + kblk[s + 1] * 64) * 512 + kvh * 128
                : V + (size_t)(b * 4096 + kblk[0] * 64) * 512 + kvh * 128;
#pragma unroll
            for (int it = 0; it < 8; it++) {
                int f = tid + it * 256;
                kreg[it] = *(const float4*)(src + (size_t)(f >> 5) * 512 + (f & 31) * 4);
            }
        }

        // mma: warp tile 16x32, k-steps 16
        float acc[4][4];
#pragma unroll
        for (int nt = 0; nt < 4; nt++)
#pragma unroll
            for (int i = 0; i < 4; i++) acc[nt][i] = 0.f;

#pragma unroll
        for (int k = 0; k < 16; k++) {
            const int col = k * 8 + lc;
            uint32_t a[4];
            const float* ap = Qs + (wm16 + lr) * 132 + col;
            a[0] = __float_as_uint(ap[0]);
            a[1] = __float_as_uint(ap[8 * 132]);
            a[2] = __float_as_uint(ap[4]);
            a[3] = __float_as_uint(ap[8 * 132 + 4]);
#pragma unroll
            for (int nt = 0; nt < 4; nt++) {
                const float* bp = KVs + (wn32 + nt * 8 + lr) * 132 + col;
                uint32_t bb[2] = { __float_as_uint(bp[0]), __float_as_uint(bp[4]) };
                mma_tf32(acc[nt], a, bb);
            }
        }

        // epilogue: scale + mask + causal -> Ps[64][516]
        const int r0 = wm16 + lr;
        if (kvalid[s]) {
            const float* mrow = mask + (size_t)b * 4096 + kblk[s] * 64;
            const bool cz = (s == 3);
#pragma unroll
            for (int nt = 0; nt < 4; nt++) {
                const int c = wn32 + nt * 8 + 2 * lc;
                const float mv0 = (1.0f - __ldg(mrow + c)) * NEGV;
                const float mv1 = (1.0f - __ldg(mrow + c + 1)) * NEGV;
                float v0 = acc[nt][0] * SCALEV + mv0;
                float v1 = acc[nt][1] * SCALEV + mv1;
                float v2 = acc[nt][2] * SCALEV + mv0;
                float v3 = acc[nt][3] * SCALEV + mv1;
                if (cz) {
                    if (c     > r0)     v0 += NEGV;
                    if (c + 1 > r0)     v1 += NEGV;
                    if (c     > r0 + 8) v2 += NEGV;
                    if (c + 1 > r0 + 8) v3 += NEGV;
                }
                *(float2*)(Ps + (size_t)r0 * 516 + s * 64 + c)       = make_float2(v0, v1);
                *(float2*)(Ps + (size_t)(r0 + 8) * 516 + s * 64 + c) = make_float2(v2, v3);
            }
        } else {
#pragma unroll
            for (int nt = 0; nt < 4; nt++) {
                const int c = wn32 + nt * 8 + 2 * lc;
                *(float2*)(Ps + (size_t)r0 * 516 + s * 64 + c)       = make_float2(NEGV, NEGV);
                *(float2*)(Ps + (size_t)(r0 + 8) * 516 + s * 64 + c) = make_float2(NEGV, NEGV);
            }
        }
        __syncthreads();   // KVs consumed before next stage
    }

    // ================= Phase B: softmax (4 threads / row) =================
    {
        const int row = tid >> 2, q = tid & 3;
        float* pr = Ps + (size_t)row * 516;
        float m = -3.4e38f;
#pragma unroll 8
        for (int c = q; c < 512; c += 4) m = fmaxf(m, pr[c]);
        m = fmaxf(m, __shfl_xor_sync(0xffffffffu, m, 1));
        m = fmaxf(m, __shfl_xor_sync(0xffffffffu, m, 2));
        float ssum = 0.f;
#pragma unroll 8
        for (int c = q; c < 512; c += 4) {
            float e = __expf(pr[c] - m);
            ssum += e;
            pr[c] = rna_tf32(e);
        }
        ssum += __shfl_xor_sync(0xffffffffu, ssum, 1);
        ssum += __shfl_xor_sync(0xffffffffu, ssum, 2);
        if (q == 0) rinv[row] = 1.0f / ssum;
    }
    __syncthreads();

    // ================= Phase C: O = P V =================
    float oacc[4][2][4];
#pragma unroll
    for (int mt = 0; mt < 4; mt++)
#pragma unroll
        for (int nt = 0; nt < 2; nt++)
#pragma unroll
            for (int i = 0; i < 4; i++) oacc[mt][nt][i] = 0.f;

    const int w16 = warp * 16;

    for (int s = 0; s < 8; s++) {
        // stage V slot s (rounded to tf32 grid), stride 136
#pragma unroll
        for (int it = 0; it < 8; it++) {
            int f = tid + it * 256;
            float4 v = kreg[it];
            v.x = rna_tf32(v.x); v.y = rna_tf32(v.y);
            v.z = rna_tf32(v.z); v.w = rna_tf32(v.w);
            *(float4*)(KVs + (f >> 5) * 136 + (f & 31) * 4) = v;
        }
        __syncthreads();
        if (s < 7) {
            const float* Vsrc = V + (size_t)(b * 4096 + kblk[s + 1] * 64) * 512 + kvh * 128;
#pragma unroll
            for (int it = 0; it < 8; it++) {
                int f = tid + it * 256;
                kreg[it] = *(const float4*)(Vsrc + (size_t)(f >> 5) * 512 + (f & 31) * 4);
            }
        }

#pragma unroll
        for (int k = 0; k < 8; k++) {
            uint32_t a[4][4];
#pragma unroll
            for (int mt = 0; mt < 4; mt++) {
                const float* ap = Ps + (size_t)(mt * 16 + lr) * 516 + s * 64 + k * 8 + lc;
                a[mt][0] = __float_as_uint(ap[0]);
                a[mt][1] = __float_as_uint(ap[8 * 516]);
                a[mt][2] = __float_as_uint(ap[4]);
                a[mt][3] = __float_as_uint(ap[8 * 516 + 4]);
            }
#pragma unroll
            for (int nt = 0; nt < 2; nt++) {
                uint32_t bb[2] = {
                    __float_as_uint(KVs[(size_t)(k * 8 + lc) * 136 + w16 + nt * 8 + lr]),
                    __float_as_uint(KVs[(size_t)(k * 8 + lc + 4) * 136 + w16 + nt * 8 + lr])
                };
#pragma unroll
                for (int mt = 0; mt < 4; mt++)
                    mma_tf32(oacc[mt][nt], a[mt], bb);
            }
        }
        __syncthreads();
    }

    // epilogue: normalize + write (rounded — feeds tf32 Wo GEMM)
    float* aop = AO + (size_t)(b * 4096 + qb * 64) * 2048 + h * 128 + w16;
#pragma unroll
    for (int mt = 0; mt < 4; mt++) {
        const int r = mt * 16 + lr;
        const float ri0 = rinv[r], ri1 = rinv[r + 8];
#pragma unroll
        for (int nt = 0; nt < 2; nt++) {
            const int c = nt * 8 + 2 * lc;
            *(float2*)(aop + (size_t)r * 2048 + c) =
                make_float2(rna_tf32(oacc[mt][nt][0] * ri0), rna_tf32(oacc[mt][nt][1] * ri0));
            *(float2*)(aop + (size_t)(r + 8) * 2048 + c) =
                make_float2(rna_tf32(oacc[mt][nt][2] * ri1), rna_tf32(oacc[mt][nt][3] * ri1));
        }
    }
}

// ---------------------------------------------------------------------------
extern "C" void kernel_launch(void* const* d_in, const int* in_sizes, int n_in,
                              void* d_out, int out_size)
{
    const float* hidden = (const float*)d_in[0];
    const float* cosp   = (const float*)d_in[1];
    const float* sinp   = (const float*)d_in[2];
    const float* maskp  = (const float*)d_in[3];
    const float* Wq     = (const float*)d_in[4];
    const float* Wk     = (const float*)d_in[5];
    const float* Wv     = (const float*)d_in[6];
    const float* Wo     = (const float*)d_in[7];
    float* out = (float*)d_out;

    float *Qp, *Kp, *Vp, *AOp, *Xr, *WqT, *WkT, *WvT, *WoT;
    cudaGetSymbolAddress((void**)&Qp, g_Q);
    cudaGetSymbolAddress((void**)&Kp, g_K);
    cudaGetSymbolAddress((void**)&Vp, g_V);
    cudaGetSymbolAddress((void**)&AOp, g_AO);
    cudaGetSymbolAddress((void**)&Xr, g_Xr);
    cudaGetSymbolAddress((void**)&WqT, g_WqT);
    cudaGetSymbolAddress((void**)&WkT, g_WkT);
    cudaGetSymbolAddress((void**)&WvT, g_WvT);
    cudaGetSymbolAddress((void**)&WoT, g_WoT);

    cudaFuncSetAttribute(attn_mma, cudaFuncAttributeMaxDynamicSharedMemorySize,
                         ATTN_SMEM_BYTES);
    cudaFuncSetAttribute(gemm_mma, cudaFuncAttributeMaxDynamicSharedMemorySize,
                         GSM_BYTES);

    // prep: round hidden, transpose+round weights (tf32 grid)
    const int n4 = 2 * 4096 * 2048 / 4;
    round_copy<<<(n4 + 255) / 256, 256>>>(hidden, Xr, n4);
    transpose_round<<<dim3(2048 / 32, 2048 / 32), dim3(32, 8)>>>(Wq, WqT, 2048, 2048);
    transpose_round<<<dim3(512 / 32, 2048 / 32), dim3(32, 8)>>>(Wk, WkT, 2048, 512);
    transpose_round<<<dim3(512 / 32, 2048 / 32), dim3(32, 8)>>>(Wv, WvT, 2048, 512);
    transpose_round<<<dim3(2048 / 32, 2048 / 32), dim3(32, 8)>>>(Wo, WoT, 2048, 2048);

    // projections (HMMA tf32)
    gemm_mma<<<dim3(16, 64), 256, GSM_BYTES>>>(Xr, WqT, Qp, 8192, 2048, 2048);
    gemm_mma<<<dim3(4, 64), 256, GSM_BYTES>>>(Xr, WkT, Kp, 8192, 512, 2048);
    gemm_mma<<<dim3(4, 64), 256, GSM_BYTES>>>(Xr, WvT, Vp, 8192, 512, 2048);

    // rope (writes tf32-rounded)
    rope_kernel<<<8192, dim3(64, 16)>>>(Qp, cosp, sinp, 16);
    rope_kernel<<<8192, dim3(64, 4)>>>(Kp, cosp, sinp, 4);

    // tensor-core block-sparse attention
    attn_mma<<<dim3(64, 16, 2), 256, ATTN_SMEM_BYTES>>>(Qp, Kp, Vp, maskp, AOp);

    // output projection (HMMA tf32)
    gemm_mma<<<dim3(16, 64), 256, GSM_BYTES>>>(AOp, WoT, out, 8192, 2048, 2048);
}

// round 9
// speedup vs baseline: 4.1463x; 1.1717x over previous
#include <cuda_runtime.h>
#include <cuda_fp16.h>
#include <math.h>
#include <stdint.h>

// B=2, S=4096, HID=2048, H=16, KV=4, D=128, BS=64, L=4, G=4, STRIDE=4, WTOK=2048
#define NEGV (-1000000000.0f)
#define SCALEV 0.08838834764831845f   // 1/sqrt(128)

// ---------------- scratch (__device__ globals; allocation-free rule) -------
__device__ __align__(1024) float  g_Q  [2 * 4096 * 2048];   // fp32 Q proj (pre-rope)
__device__ __align__(1024) float  g_K  [2 * 4096 * 512];    // fp32 K proj (pre-rope)
__device__ __align__(1024) __half g_Qh [2 * 4096 * 2048];   // fp16 Q (post-rope)
__device__ __align__(1024) __half g_Kh [2 * 4096 * 512];    // fp16 K (post-rope)
__device__ __align__(1024) __half g_Vh [2 * 4096 * 512];    // fp16 V
__device__ __align__(1024) __half g_AOh[2 * 4096 * 2048];   // fp16 attention out
__device__ __align__(1024) __half g_Xh [2 * 4096 * 2048];   // fp16 hidden
__device__ __align__(1024) __half g_WqT[2048 * 2048];
__device__ __align__(1024) __half g_WkT[512 * 2048];
__device__ __align__(1024) __half g_WvT[512 * 2048];
__device__ __align__(1024) __half g_WoT[2048 * 2048];

// ---------------- helpers ---------------------------------------------------
__device__ __forceinline__ uint32_t smem_u32(const void* p) {
    uint32_t a;
    asm("{ .reg .u64 t; cvta.to.shared.u64 t, %1; cvt.u32.u64 %0, t; }" : "=r"(a) : "l"(p));
    return a;
}
#define CP_ASYNC16(sm, gm) \
    asm volatile("cp.async.cg.shared.global [%0], [%1], 16;" :: "r"(sm), "l"(gm) : "memory")
#define CP_COMMIT() asm volatile("cp.async.commit_group;" ::: "memory")
#define CP_WAIT0()  asm volatile("cp.async.wait_group 0;" ::: "memory")
#define CP_WAIT1()  asm volatile("cp.async.wait_group 1;" ::: "memory")

__device__ __forceinline__ void mma_f16(float c[4], const uint32_t a[4], uint32_t b0, uint32_t b1) {
    asm volatile(
        "mma.sync.aligned.m16n8k16.row.col.f32.f16.f16.f32 "
        "{%0,%1,%2,%3}, {%4,%5,%6,%7}, {%8,%9}, {%0,%1,%2,%3};"
        : "+f"(c[0]), "+f"(c[1]), "+f"(c[2]), "+f"(c[3])
        : "r"(a[0]), "r"(a[1]), "r"(a[2]), "r"(a[3]), "r"(b0), "r"(b1));
}
__device__ __forceinline__ void ldsm4(uint32_t r[4], uint32_t addr) {
    asm volatile("ldmatrix.sync.aligned.m8n8.x4.shared.b16 {%0,%1,%2,%3}, [%4];"
                 : "=r"(r[0]), "=r"(r[1]), "=r"(r[2]), "=r"(r[3]) : "r"(addr));
}
__device__ __forceinline__ void ldsm4t(uint32_t r[4], uint32_t addr) {
    asm volatile("ldmatrix.sync.aligned.m8n8.x4.trans.shared.b16 {%0,%1,%2,%3}, [%4];"
                 : "=r"(r[0]), "=r"(r[1]), "=r"(r[2]), "=r"(r[3]) : "r"(addr));
}
__device__ __forceinline__ uint32_t packh2(float x, float y) {
    __half2 h = __floats2half2_rn(x, y);
    return *(uint32_t*)&h;
}

// ---------------------------------------------------------------------------
// fp16 HMMA GEMM: C[M,N] = A[M,K] * Bt[N,K]^T (A,Bt half; C fp32 or half).
// 128x128x64 CTA tile, 256 threads, warp tile 64x32, cp.async double buffer.
// smem pitch 72 halves (144B): 8-row ldmatrix sets span 32 distinct banks.
// ---------------------------------------------------------------------------
#define HPITCH 72
#define HSTG   (128 * HPITCH)                 // halves per tile per stage
#define GSMH_BYTES (2 * HSTG * 2 * 2)         // A+B, 2 stages, 2B each = 73728

template <bool OUT_HALF>
__global__ __launch_bounds__(256, 2) void gemm_h(
    const __half* __restrict__ A, const __half* __restrict__ Bt, void* __restrict__ Cv,
    int M, int N, int K)
{
    extern __shared__ __half smh[];
    const uint32_t smbA = smem_u32(smh);
    const uint32_t smbB = smbA + 2 * HSTG * 2;   // bytes

    const int tid  = threadIdx.x;
    const int lane = tid & 31;
    const int warp = tid >> 5;
    const int wm = warp & 1;              // 0..1 (64-row half)
    const int wn = warp >> 1;             // 0..3 (32-col quarter)
    const int lr = lane >> 2;             // 0..7
    const int lc = lane & 3;              // 0..3
    const int crow0 = blockIdx.y * 128;
    const int ccol0 = blockIdx.x * 128;

    const int ldrow = tid >> 3;           // 0..31
    const int ldc   = tid & 7;            // 16B chunk (8 halves) in 64-half row

    float acc[4][4][4];
#pragma unroll
    for (int mt = 0; mt < 4; mt++)
#pragma unroll
        for (int nt = 0; nt < 4; nt++)
#pragma unroll
            for (int i = 0; i < 4; i++) acc[mt][nt][i] = 0.f;

    const int T = K >> 6;   // BK = 64

#define GLOADH(buf, k0)                                                                \
    do {                                                                               \
        _Pragma("unroll")                                                              \
        for (int it = 0; it < 4; it++) {                                               \
            const int row = ldrow + it * 32;                                           \
            const uint32_t so = (uint32_t)(((buf) * HSTG + row * HPITCH + ldc * 8) * 2); \
            CP_ASYNC16(smbA + so, A  + (size_t)(crow0 + row) * K + (k0) + ldc * 8);    \
            CP_ASYNC16(smbB + so, Bt + (size_t)(ccol0 + row) * K + (k0) + ldc * 8);    \
        }                                                                              \
    } while (0)

    GLOADH(0, 0);
    CP_COMMIT();

    const int aRowBase = wm * 64 + (lane & 15);
    const int aKoff    = (lane >> 4) * 8;
    const int bRowBase = wn * 32 + (lane & 7) + ((lane >> 4) & 1) * 8;
    const int bKoff    = ((lane >> 3) & 1) * 8;

    for (int t = 0; t < T; t++) {
        const int buf = t & 1;
        if (t + 1 < T) {
            GLOADH(buf ^ 1, (t + 1) << 6);
            CP_COMMIT();
            CP_WAIT1();
        } else {
            CP_WAIT0();
        }
        __syncthreads();

        const uint32_t Ab = smbA + buf * HSTG * 2;
        const uint32_t Bb = smbB + buf * HSTG * 2;
#pragma unroll
        for (int kk = 0; kk < 4; kk++) {
            uint32_t a[4][4];
#pragma unroll
            for (int mt = 0; mt < 4; mt++)
                ldsm4(a[mt], Ab + ((aRowBase + mt * 16) * HPITCH + kk * 16 + aKoff) * 2);
            uint32_t br[2][4];
#pragma unroll
            for (int nt2 = 0; nt2 < 2; nt2++)
                ldsm4(br[nt2], Bb + ((bRowBase + nt2 * 16) * HPITCH + kk * 16 + bKoff) * 2);
#pragma unroll
            for (int mt = 0; mt < 4; mt++)
#pragma unroll
                for (int nt = 0; nt < 4; nt++)
                    mma_f16(acc[mt][nt], a[mt], br[nt >> 1][(nt & 1) * 2], br[nt >> 1][(nt & 1) * 2 + 1]);
        }
        __syncthreads();
    }

#pragma unroll
    for (int mt = 0; mt < 4; mt++) {
        const int row = crow0 + wm * 64 + mt * 16 + lr;
#pragma unroll
        for (int nt = 0; nt < 4; nt++) {
            const int col = ccol0 + wn * 32 + nt * 8 + 2 * lc;
            if (OUT_HALF) {
                __half* C = (__half*)Cv;
                *(uint32_t*)(C + (size_t)row * N + col)       = packh2(acc[mt][nt][0], acc[mt][nt][1]);
                *(uint32_t*)(C + (size_t)(row + 8) * N + col) = packh2(acc[mt][nt][2], acc[mt][nt][3]);
            } else {
                float* C = (float*)Cv;
                *(float2*)(C + (size_t)row * N + col)       = make_float2(acc[mt][nt][0], acc[mt][nt][1]);
                *(float2*)(C + (size_t)(row + 8) * N + col) = make_float2(acc[mt][nt][2], acc[mt][nt][3]);
            }
        }
    }
}

// ---------------------------------------------------------------------------
// prep kernels
// ---------------------------------------------------------------------------
__global__ void round_half(const float* __restrict__ src, __half* __restrict__ dst, int n8) {
    int i = blockIdx.x * blockDim.x + threadIdx.x;
    if (i < n8) {
        float4 v0 = ((const float4*)src)[2 * i];
        float4 v1 = ((const float4*)src)[2 * i + 1];
        uint4 o;
        o.x = packh2(v0.x, v0.y); o.y = packh2(v0.z, v0.w);
        o.z = packh2(v1.x, v1.y); o.w = packh2(v1.z, v1.w);
        ((uint4*)dst)[i] = o;
    }
}
// W [K,N] fp32 -> Wt [N,K] half. blockDim (32,8), grid (N/32, K/32).
__global__ void transpose_half(const float* __restrict__ W, __half* __restrict__ Wt,
                               int K, int N) {
    __shared__ float t[32][33];
    const int n0 = blockIdx.x * 32, k0 = blockIdx.y * 32;
    const int x = threadIdx.x, y = threadIdx.y;
#pragma unroll
    for (int j = 0; j < 32; j += 8)
        t[y + j][x] = W[(size_t)(k0 + y + j) * N + n0 + x];
    __syncthreads();
#pragma unroll
    for (int j = 0; j < 32; j += 8)
        Wt[(size_t)(n0 + y + j) * K + k0 + x] = __float2half_rn(t[x][y + j]);
}

// ---------------------------------------------------------------------------
// RoPE: read fp32 X, write fp16 Xh. blockDim (64, nh), grid B*S.
// ---------------------------------------------------------------------------
__global__ void rope_half(const float* __restrict__ X, __half* __restrict__ Xh,
                          const float* __restrict__ cosp, const float* __restrict__ sinp, int nh)
{
    const int row = blockIdx.x;
    const int h = threadIdx.y;
    const int d = threadIdx.x;
    const float c1 = cosp[row * 128 + d];
    const float s1 = sinp[row * 128 + d];
    const float c2 = cosp[row * 128 + d + 64];
    const float s2 = sinp[row * 128 + d + 64];
    const float* xp = X + (size_t)row * (nh * 128) + h * 128;
    __half* op = Xh + (size_t)row * (nh * 128) + h * 128;
    const float x1 = xp[d], x2 = xp[d + 64];
    op[d]      = __float2half_rn(x1 * c1 - x2 * s1);
    op[d + 64] = __float2half_rn(x2 * c2 + x1 * s2);
}

// ---------------------------------------------------------------------------
// fp16 tensor-core block-sparse attention. One CTA per (qblock, head, batch).
// 256 threads / 8 warps, mma.m16n8k16.f16.
// smem: Ps fp32 [64][520] | Qs half [64][136] | KVs half [64][136] | rinv[64]
// Pitches: 520 fp32 (== 8 mod 32 banks) and 136 half (272B, == 4 mod 32 banks)
// make all fragment/ldmatrix accesses bank-conflict-free.
// ---------------------------------------------------------------------------
#define PSP   520
#define HQP   136
#define APS_F 0
#define AQS_F (64 * PSP)                   // 33280 floats
#define AKV_F (AQS_F + 64 * HQP / 2)       // +4352
#define ARI_F (AKV_F + 64 * HQP / 2)       // +4352
#define ATTN_SMEM_BYTES ((ARI_F + 64) * 4) // 168192

__global__ __launch_bounds__(256, 1) void attn_h(
    const __half* __restrict__ Q, const __half* __restrict__ K, const __half* __restrict__ V,
    const float* __restrict__ mask, __half* __restrict__ AO)
{
    extern __shared__ float smf[];
    float*  Ps   = smf + APS_F;
    __half* Qs   = (__half*)(smf + AQS_F);
    __half* KVs  = (__half*)(smf + AKV_F);
    float*  rinv = smf + ARI_F;
    const uint32_t Qaddr  = smem_u32(Qs);
    const uint32_t KVaddr = smem_u32(KVs);

    const int qb = blockIdx.x;
    const int h  = blockIdx.y;
    const int b  = blockIdx.z;
    const int kvh = h >> 2;
    const int tid = threadIdx.x;
    const int lane = tid & 31;
    const int warp = tid >> 5;
    const int lr = lane >> 2;       // 0..7
    const int lc = lane & 3;        // 0..3

    // --- key-block table: 4 local (self = slot 3) + 4 strided global ---
    int kblk[8]; bool kvalid[8];
#pragma unroll
    for (int w = 0; w < 4; w++) {
        int jb = qb - 3 + w;
        kblk[w] = jb < 0 ? 0 : jb;
        kvalid[w] = (jb >= 0);
    }
    {
        int start = qb - 32; if (start < 0) start = 0;
        int cnt = (qb > start) ? ((qb - start + 3) >> 2) : 0;
        int first = (cnt > 4) ? (cnt - 4) : 0;
        int sz = (cnt < 4) ? cnt : 4;
        int s0 = 4 - sz;
#pragma unroll
        for (int g = 0; g < 4; g++) {
            if (g < s0) { kblk[4 + g] = 0; kvalid[4 + g] = false; }
            else        { kblk[4 + g] = start + 4 * (first + g - s0); kvalid[4 + g] = true; }
        }
    }

    // --- stage Q (64x128 half, pitch 136) + prefetch K slot 0 into regs ---
    uint4 kreg[4];
    {
        const __half* Qsrc = Q + (size_t)(b * 4096 + qb * 64) * 2048 + h * 128;
#pragma unroll
        for (int it = 0; it < 4; it++) {
            int f = tid + it * 256;
            int row = f >> 4, c = f & 15;
            *(uint4*)(Qs + row * HQP + c * 8) = *(const uint4*)(Qsrc + (size_t)row * 2048 + c * 8);
        }
        const __half* Ksrc = K + (size_t)(b * 4096 + kblk[0] * 64) * 512 + kvh * 128;
#pragma unroll
        for (int it = 0; it < 4; it++) {
            int f = tid + it * 256;
            kreg[it] = *(const uint4*)(Ksrc + (size_t)(f >> 4) * 512 + (f & 15) * 8);
        }
    }
    __syncthreads();

    // ================= Phase A: S = Q K^T, per slot =================
    const int wm16 = (warp >> 1) * 16;   // row group
    const int wn32 = (warp & 1) * 32;    // col group
    const int aRow = wm16 + (lane & 15);
    const int aKoff = (lane >> 4) * 8;
    const int bRow = (lane & 7) + ((lane >> 4) & 1) * 8;
    const int bKoff = ((lane >> 3) & 1) * 8;

    for (int s = 0; s < 8; s++) {
        // stage K slot s (regs -> smem, pitch 136)
#pragma unroll
        for (int it = 0; it < 4; it++) {
            int f = tid + it * 256;
            *(uint4*)(KVs + (f >> 4) * HQP + (f & 15) * 8) = kreg[it];
        }
        __syncthreads();
        // prefetch next K (or V slot 0 at the end)
        {
            const __half* src = (s < 7)
                ? K + (size_t)(b * 4096 + kblk[s + 1] * 64) * 512 + kvh * 128
                : V + (size_t)(b * 4096 + kblk[0] * 64) * 512 + kvh * 128;
#pragma unroll
            for (int it = 0; it < 4; it++) {
                int f = tid + it * 256;
                kreg[it] = *(const uint4*)(src + (size_t)(f >> 4) * 512 + (f & 15) * 8);
            }
        }

        float acc[4][4];
#pragma unroll
        for (int nt = 0; nt < 4; nt++)
#pragma unroll
            for (int i = 0; i < 4; i++) acc[nt][i] = 0.f;

#pragma unroll
        for (int kk = 0; kk < 8; kk++) {
            uint32_t a[4];
            ldsm4(a, Qaddr + (aRow * HQP + kk * 16 + aKoff) * 2);
            uint32_t br[2][4];
#pragma unroll
            for (int nt2 = 0; nt2 < 2; nt2++)
                ldsm4(br[nt2], KVaddr + ((wn32 + nt2 * 16 + bRow) * HQP + kk * 16 + bKoff) * 2);
#pragma unroll
            for (int nt = 0; nt < 4; nt++)
                mma_f16(acc[nt], a, br[nt >> 1][(nt & 1) * 2], br[nt >> 1][(nt & 1) * 2 + 1]);
        }

        // epilogue: scale + mask + causal -> Ps (fp32, pitch 520)
        const int r0 = wm16 + lr;
        if (kvalid[s]) {
            const float* mrow = mask + (size_t)b * 4096 + kblk[s] * 64;
            const bool cz = (s == 3);
#pragma unroll
            for (int nt = 0; nt < 4; nt++) {
                const int c = wn32 + nt * 8 + 2 * lc;
                const float mv0 = (1.0f - __ldg(mrow + c)) * NEGV;
                const float mv1 = (1.0f - __ldg(mrow + c + 1)) * NEGV;
                float v0 = acc[nt][0] * SCALEV + mv0;
                float v1 = acc[nt][1] * SCALEV + mv1;
                float v2 = acc[nt][2] * SCALEV + mv0;
                float v3 = acc[nt][3] * SCALEV + mv1;
                if (cz) {
                    if (c     > r0)     v0 += NEGV;
                    if (c + 1 > r0)     v1 += NEGV;
                    if (c     > r0 + 8) v2 += NEGV;
                    if (c + 1 > r0 + 8) v3 += NEGV;
                }
                *(float2*)(Ps + (size_t)r0 * PSP + s * 64 + c)       = make_float2(v0, v1);
                *(float2*)(Ps + (size_t)(r0 + 8) * PSP + s * 64 + c) = make_float2(v2, v3);
            }
        } else {
#pragma unroll
            for (int nt = 0; nt < 4; nt++) {
                const int c = wn32 + nt * 8 + 2 * lc;
                *(float2*)(Ps + (size_t)r0 * PSP + s * 64 + c)       = make_float2(NEGV, NEGV);
                *(float2*)(Ps + (size_t)(r0 + 8) * PSP + s * 64 + c) = make_float2(NEGV, NEGV);
            }
        }
        __syncthreads();   // KVs consumed before next stage
    }

    // ================= Phase B: softmax (4 threads / row) =================
    {
        const int row = tid >> 2, q = tid & 3;
        float* pr = Ps + (size_t)row * PSP;
        float m = -3.4e38f;
#pragma unroll 8
        for (int c = q; c < 512; c += 4) m = fmaxf(m, pr[c]);
        m = fmaxf(m, __shfl_xor_sync(0xffffffffu, m, 1));
        m = fmaxf(m, __shfl_xor_sync(0xffffffffu, m, 2));
        float ssum = 0.f;
#pragma unroll 8
        for (int c = q; c < 512; c += 4) {
            float e = __expf(pr[c] - m);
            ssum += e;
            pr[c] = e;
        }
        ssum += __shfl_xor_sync(0xffffffffu, ssum, 1);
        ssum += __shfl_xor_sync(0xffffffffu, ssum, 2);
        if (q == 0) rinv[row] = 1.0f / ssum;
    }
    __syncthreads();

    // ================= Phase C: O = P V =================
    float oacc[4][2][4];
#pragma unroll
    for (int mt = 0; mt < 4; mt++)
#pragma unroll
        for (int nt = 0; nt < 2; nt++)
#pragma unroll
            for (int i = 0; i < 4; i++) oacc[mt][nt][i] = 0.f;

    const int w16 = warp * 16;
    const int vKrow = (lane & 7) + ((lane >> 3) & 1) * 8;
    const int vDoff = w16 + ((lane >> 4) & 1) * 8;

    for (int s = 0; s < 8; s++) {
        // stage V slot s (pitch 136)
#pragma unroll
        for (int it = 0; it < 4; it++) {
            int f = tid + it * 256;
            *(uint4*)(KVs + (f >> 4) * HQP + (f & 15) * 8) = kreg[it];
        }
        __syncthreads();
        if (s < 7) {
            const __half* Vsrc = V + (size_t)(b * 4096 + kblk[s + 1] * 64) * 512 + kvh * 128;
#pragma unroll
            for (int it = 0; it < 4; it++) {
                int f = tid + it * 256;
                kreg[it] = *(const uint4*)(Vsrc + (size_t)(f >> 4) * 512 + (f & 15) * 8);
            }
        }

#pragma unroll
        for (int kk = 0; kk < 4; kk++) {
            // B: V via ldmatrix.trans (k-major pairs at column d)
            uint32_t bv[4];
            ldsm4t(bv, KVaddr + ((kk * 16 + vKrow) * HQP + vDoff) * 2);
            // A: P from fp32 Ps, packed to half
            const int kb = s * 64 + kk * 16 + 2 * lc;
#pragma unroll
            for (int mt = 0; mt < 4; mt++) {
                const int r = mt * 16 + lr;
                float2 f0 = *(float2*)(Ps + (size_t)r * PSP + kb);
                float2 f1 = *(float2*)(Ps + (size_t)(r + 8) * PSP + kb);
                float2 f2 = *(float2*)(Ps + (size_t)r * PSP + kb + 8);
                float2 f3 = *(float2*)(Ps + (size_t)(r + 8) * PSP + kb + 8);
                uint32_t a[4] = { packh2(f0.x, f0.y), packh2(f1.x, f1.y),
                                  packh2(f2.x, f2.y), packh2(f3.x, f3.y) };
                mma_f16(oacc[mt][0], a, bv[0], bv[1]);
                mma_f16(oacc[mt][1], a, bv[2], bv[3]);
            }
        }
        __syncthreads();
    }

    // epilogue: normalize + write half (feeds fp16 Wo GEMM)
    __half* aop = AO + (size_t)(b * 4096 + qb * 64) * 2048 + h * 128 + w16;
#pragma unroll
    for (int mt = 0; mt < 4; mt++) {
        const int r = mt * 16 + lr;
        const float ri0 = rinv[r], ri1 = rinv[r + 8];
#pragma unroll
        for (int nt = 0; nt < 2; nt++) {
            const int c = nt * 8 + 2 * lc;
            *(uint32_t*)(aop + (size_t)r * 2048 + c) =
                packh2(oacc[mt][nt][0] * ri0, oacc[mt][nt][1] * ri0);
            *(uint32_t*)(aop + (size_t)(r + 8) * 2048 + c) =
                packh2(oacc[mt][nt][2] * ri1, oacc[mt][nt][3] * ri1);
        }
    }
}

// ---------------------------------------------------------------------------
extern "C" void kernel_launch(void* const* d_in, const int* in_sizes, int n_in,
                              void* d_out, int out_size)
{
    const float* hidden = (const float*)d_in[0];
    const float* cosp   = (const float*)d_in[1];
    const float* sinp   = (const float*)d_in[2];
    const float* maskp  = (const float*)d_in[3];
    const float* Wq     = (const float*)d_in[4];
    const float* Wk     = (const float*)d_in[5];
    const float* Wv     = (const float*)d_in[6];
    const float* Wo     = (const float*)d_in[7];
    float* out = (float*)d_out;

    float *Qp, *Kp;
    __half *Qh, *Kh, *Vh, *AOh, *Xh, *WqT, *WkT, *WvT, *WoT;
    cudaGetSymbolAddress((void**)&Qp, g_Q);
    cudaGetSymbolAddress((void**)&Kp, g_K);
    cudaGetSymbolAddress((void**)&Qh, g_Qh);
    cudaGetSymbolAddress((void**)&Kh, g_Kh);
    cudaGetSymbolAddress((void**)&Vh, g_Vh);
    cudaGetSymbolAddress((void**)&AOh, g_AOh);
    cudaGetSymbolAddress((void**)&Xh, g_Xh);
    cudaGetSymbolAddress((void**)&WqT, g_WqT);
    cudaGetSymbolAddress((void**)&WkT, g_WkT);
    cudaGetSymbolAddress((void**)&WvT, g_WvT);
    cudaGetSymbolAddress((void**)&WoT, g_WoT);

    cudaFuncSetAttribute(attn_h, cudaFuncAttributeMaxDynamicSharedMemorySize,
                         ATTN_SMEM_BYTES);
    cudaFuncSetAttribute(gemm_h<false>, cudaFuncAttributeMaxDynamicSharedMemorySize,
                         GSMH_BYTES);
    cudaFuncSetAttribute(gemm_h<true>, cudaFuncAttributeMaxDynamicSharedMemorySize,
                         GSMH_BYTES);

    // prep: hidden -> half, transpose weights -> half
    const int n8 = 2 * 4096 * 2048 / 8;
    round_half<<<(n8 + 255) / 256, 256>>>(hidden, Xh, n8);
    transpose_half<<<dim3(2048 / 32, 2048 / 32), dim3(32, 8)>>>(Wq, WqT, 2048, 2048);
    transpose_half<<<dim3(512 / 32, 2048 / 32), dim3(32, 8)>>>(Wk, WkT, 2048, 512);
    transpose_half<<<dim3(512 / 32, 2048 / 32), dim3(32, 8)>>>(Wv, WvT, 2048, 512);
    transpose_half<<<dim3(2048 / 32, 2048 / 32), dim3(32, 8)>>>(Wo, WoT, 2048, 2048);

    // projections (fp16 HMMA): Q,K -> fp32 (rope needs fp32 in), V -> half
    gemm_h<false><<<dim3(16, 64), 256, GSMH_BYTES>>>(Xh, WqT, Qp, 8192, 2048, 2048);
    gemm_h<false><<<dim3(4, 64), 256, GSMH_BYTES>>>(Xh, WkT, Kp, 8192, 512, 2048);
    gemm_h<true><<<dim3(4, 64), 256, GSMH_BYTES>>>(Xh, WvT, Vh, 8192, 512, 2048);

    // rope: fp32 in -> fp16 out
    rope_half<<<8192, dim3(64, 16)>>>(Qp, Qh, cosp, sinp, 16);
    rope_half<<<8192, dim3(64, 4)>>>(Kp, Kh, cosp, sinp, 4);

    // fp16 tensor-core block-sparse attention
    attn_h<<<dim3(64, 16, 2), 256, ATTN_SMEM_BYTES>>>(Qh, Kh, Vh, maskp, AOh);

    // output projection (fp16 HMMA, fp32 out)
    gemm_h<false><<<dim3(16, 64), 256, GSMH_BYTES>>>(AOh, WoT, out, 8192, 2048, 2048);
}

// round 10
// speedup vs baseline: 6.1745x; 1.4892x over previous
#include <cuda_runtime.h>
#include <cuda_fp16.h>
#include <math.h>
#include <stdint.h>

// B=2, S=4096, HID=2048, H=16, KV=4, D=128, BS=64, L=4, G=4, STRIDE=4, WTOK=2048
#define NEGV (-1000000000.0f)
#define SCALEV 0.08838834764831845f   // 1/sqrt(128)

// ---------------- scratch (__device__ globals; allocation-free rule) -------
__device__ __align__(1024) float  g_Q  [2 * 4096 * 2048];   // fp32 Q proj (pre-rope)
__device__ __align__(1024) float  g_K  [2 * 4096 * 512];    // fp32 K proj (pre-rope)
__device__ __align__(1024) __half g_Qh [2 * 4096 * 2048];   // fp16 Q (post-rope)
__device__ __align__(1024) __half g_Kh [2 * 4096 * 512];    // fp16 K (post-rope)
__device__ __align__(1024) __half g_Vh [2 * 4096 * 512];    // fp16 V
__device__ __align__(1024) __half g_AOh[2 * 4096 * 2048];   // fp16 attention out
__device__ __align__(1024) __half g_Xh [2 * 4096 * 2048];   // fp16 hidden
__device__ __align__(1024) __half g_WqT[2048 * 2048];
__device__ __align__(1024) __half g_WkT[512 * 2048];
__device__ __align__(1024) __half g_WvT[512 * 2048];
__device__ __align__(1024) __half g_WoT[2048 * 2048];

// ---------------- helpers ---------------------------------------------------
__device__ __forceinline__ uint32_t smem_u32(const void* p) {
    uint32_t a;
    asm("{ .reg .u64 t; cvta.to.shared.u64 t, %1; cvt.u32.u64 %0, t; }" : "=r"(a) : "l"(p));
    return a;
}
#define CP_ASYNC16(sm, gm) \
    asm volatile("cp.async.cg.shared.global [%0], [%1], 16;" :: "r"(sm), "l"(gm) : "memory")
#define CP_COMMIT() asm volatile("cp.async.commit_group;" ::: "memory")
#define CP_WAIT0()  asm volatile("cp.async.wait_group 0;" ::: "memory")
#define CP_WAIT1()  asm volatile("cp.async.wait_group 1;" ::: "memory")
#define CP_WAIT2()  asm volatile("cp.async.wait_group 2;" ::: "memory")

__device__ __forceinline__ void mma_f16(float c[4], const uint32_t a[4], uint32_t b0, uint32_t b1) {
    asm volatile(
        "mma.sync.aligned.m16n8k16.row.col.f32.f16.f16.f32 "
        "{%0,%1,%2,%3}, {%4,%5,%6,%7}, {%8,%9}, {%0,%1,%2,%3};"
        : "+f"(c[0]), "+f"(c[1]), "+f"(c[2]), "+f"(c[3])
        : "r"(a[0]), "r"(a[1]), "r"(a[2]), "r"(a[3]), "r"(b0), "r"(b1));
}
__device__ __forceinline__ void ldsm4(uint32_t r[4], uint32_t addr) {
    asm volatile("ldmatrix.sync.aligned.m8n8.x4.shared.b16 {%0,%1,%2,%3}, [%4];"
                 : "=r"(r[0]), "=r"(r[1]), "=r"(r[2]), "=r"(r[3]) : "r"(addr));
}
__device__ __forceinline__ void ldsm4t(uint32_t r[4], uint32_t addr) {
    asm volatile("ldmatrix.sync.aligned.m8n8.x4.trans.shared.b16 {%0,%1,%2,%3}, [%4];"
                 : "=r"(r[0]), "=r"(r[1]), "=r"(r[2]), "=r"(r[3]) : "r"(addr));
}
__device__ __forceinline__ uint32_t packh2(float x, float y) {
    __half2 h = __floats2half2_rn(x, y);
    return *(uint32_t*)&h;
}

// ---------------------------------------------------------------------------
// fp16 HMMA GEMM: C[M,N] = A[M,K] * Bt[N,K]^T (A,Bt half; C fp32 or half).
// 128x128 CTA tile, 4 warps (128 thr), warp tile 64x64, BK=32, 4-stage cp.async.
// Pitch 40 halves (80B): ldmatrix 8-row phases hit all 32 banks exactly.
// ---------------------------------------------------------------------------
#define HP2  40
#define STGH (128 * HP2)                      // 5120 halves per matrix per stage
#define GSMH_BYTES (8 * STGH * 2)             // A+B x 4 stages = 81920 B

template <bool OUT_HALF>
__global__ __launch_bounds__(128, 2) void gemm_h(
    const __half* __restrict__ A, const __half* __restrict__ Bt, void* __restrict__ Cv,
    int M, int N, int K)
{
    extern __shared__ __half smh[];
    const uint32_t smbA = smem_u32(smh);
    const uint32_t smbB = smbA + 4 * STGH * 2;   // bytes

    const int tid  = threadIdx.x;
    const int lane = tid & 31;
    const int warp = tid >> 5;
    const int wm = warp & 1;              // 0..1 (64-row half)
    const int wn = warp >> 1;             // 0..1 (64-col half)
    const int lr = lane >> 2;             // 0..7
    const int lc = lane & 3;              // 0..3
    const int crow0 = blockIdx.y * 128;
    const int ccol0 = blockIdx.x * 128;

    const int ldrow = tid >> 2;           // 0..31
    const int ldc   = tid & 3;            // 16B chunk (8 halves) in 32-half row

    float acc[4][8][4];
#pragma unroll
    for (int mt = 0; mt < 4; mt++)
#pragma unroll
        for (int nt = 0; nt < 8; nt++)
#pragma unroll
            for (int i = 0; i < 4; i++) acc[mt][nt][i] = 0.f;

    const int T = K >> 5;   // BK = 32

#define GLOADH(buf, k0)                                                                \
    do {                                                                               \
        _Pragma("unroll")                                                              \
        for (int it = 0; it < 4; it++) {                                               \
            const int row = ldrow + it * 32;                                           \
            const uint32_t so = (uint32_t)(((buf) * STGH + row * HP2 + ldc * 8) * 2);  \
            CP_ASYNC16(smbA + so, A  + (size_t)(crow0 + row) * K + (k0) + ldc * 8);    \
            CP_ASYNC16(smbB + so, Bt + (size_t)(ccol0 + row) * K + (k0) + ldc * 8);    \
        }                                                                              \
    } while (0)

    GLOADH(0, 0);  CP_COMMIT();
    GLOADH(1, 32); CP_COMMIT();
    GLOADH(2, 64); CP_COMMIT();

    const int aRowBase = wm * 64 + (lane & 15);
    const int aKoff    = (lane >> 4) * 8;
    const int bRowBase = wn * 64 + (lane & 7) + ((lane >> 4) & 1) * 8;
    const int bKoff    = ((lane >> 3) & 1) * 8;

    for (int t = 0; t < T; t++) {
        const int rem = T - 1 - t;
        if (rem >= 2) CP_WAIT2(); else if (rem == 1) CP_WAIT1(); else CP_WAIT0();
        __syncthreads();
        if (t + 3 < T) { GLOADH((t + 3) & 3, (t + 3) << 5); CP_COMMIT(); }

        const int buf = t & 3;
        const uint32_t Ab = smbA + buf * STGH * 2;
        const uint32_t Bb = smbB + buf * STGH * 2;
#pragma unroll
        for (int kk = 0; kk < 2; kk++) {
            uint32_t a[4][4];
#pragma unroll
            for (int mt = 0; mt < 4; mt++)
                ldsm4(a[mt], Ab + ((aRowBase + mt * 16) * HP2 + kk * 16 + aKoff) * 2);
            uint32_t br[4][4];
#pragma unroll
            for (int g = 0; g < 4; g++)
                ldsm4(br[g], Bb + ((bRowBase + g * 16) * HP2 + kk * 16 + bKoff) * 2);
#pragma unroll
            for (int mt = 0; mt < 4; mt++)
#pragma unroll
                for (int nt = 0; nt < 8; nt++)
                    mma_f16(acc[mt][nt], a[mt], br[nt >> 1][(nt & 1) * 2], br[nt >> 1][(nt & 1) * 2 + 1]);
        }
    }

#pragma unroll
    for (int mt = 0; mt < 4; mt++) {
        const int row = crow0 + wm * 64 + mt * 16 + lr;
#pragma unroll
        for (int nt = 0; nt < 8; nt++) {
            const int col = ccol0 + wn * 64 + nt * 8 + 2 * lc;
            if (OUT_HALF) {
                __half* C = (__half*)Cv;
                *(uint32_t*)(C + (size_t)row * N + col)       = packh2(acc[mt][nt][0], acc[mt][nt][1]);
                *(uint32_t*)(C + (size_t)(row + 8) * N + col) = packh2(acc[mt][nt][2], acc[mt][nt][3]);
            } else {
                float* C = (float*)Cv;
                *(float2*)(C + (size_t)row * N + col)       = make_float2(acc[mt][nt][0], acc[mt][nt][1]);
                *(float2*)(C + (size_t)(row + 8) * N + col) = make_float2(acc[mt][nt][2], acc[mt][nt][3]);
            }
        }
    }
}

// ---------------------------------------------------------------------------
// prep kernels
// ---------------------------------------------------------------------------
__global__ void round_half(const float* __restrict__ src, __half* __restrict__ dst, int n8) {
    int i = blockIdx.x * blockDim.x + threadIdx.x;
    if (i < n8) {
        float4 v0 = ((const float4*)src)[2 * i];
        float4 v1 = ((const float4*)src)[2 * i + 1];
        uint4 o;
        o.x = packh2(v0.x, v0.y); o.y = packh2(v0.z, v0.w);
        o.z = packh2(v1.x, v1.y); o.w = packh2(v1.z, v1.w);
        ((uint4*)dst)[i] = o;
    }
}
// W [K,N] fp32 -> Wt [N,K] half. blockDim (32,8), grid (N/32, K/32).
__global__ void transpose_half(const float* __restrict__ W, __half* __restrict__ Wt,
                               int K, int N) {
    __shared__ float t[32][33];
    const int n0 = blockIdx.x * 32, k0 = blockIdx.y * 32;
    const int x = threadIdx.x, y = threadIdx.y;
#pragma unroll
    for (int j = 0; j < 32; j += 8)
        t[y + j][x] = W[(size_t)(k0 + y + j) * N + n0 + x];
    __syncthreads();
#pragma unroll
    for (int j = 0; j < 32; j += 8)
        Wt[(size_t)(n0 + y + j) * K + k0 + x] = __float2half_rn(t[x][y + j]);
}

// ---------------------------------------------------------------------------
// RoPE: read fp32 X, write fp16 Xh. blockDim (64, nh), grid B*S.
// ---------------------------------------------------------------------------
__global__ void rope_half(const float* __restrict__ X, __half* __restrict__ Xh,
                          const float* __restrict__ cosp, const float* __restrict__ sinp, int nh)
{
    const int row = blockIdx.x;
    const int h = threadIdx.y;
    const int d = threadIdx.x;
    const float c1 = cosp[row * 128 + d];
    const float s1 = sinp[row * 128 + d];
    const float c2 = cosp[row * 128 + d + 64];
    const float s2 = sinp[row * 128 + d + 64];
    const float* xp = X + (size_t)row * (nh * 128) + h * 128;
    __half* op = Xh + (size_t)row * (nh * 128) + h * 128;
    const float x1 = xp[d], x2 = xp[d + 64];
    op[d]      = __float2half_rn(x1 * c1 - x2 * s1);
    op[d + 64] = __float2half_rn(x2 * c2 + x1 * s2);
}

// ---------------------------------------------------------------------------
// fp16 tensor-core block-sparse attention. One CTA per (qblock, head, batch).
// 256 threads / 8 warps, mma.m16n8k16.f16. (unchanged from R9 — passed)
// ---------------------------------------------------------------------------
#define PSP   520
#define HQP   136
#define APS_F 0
#define AQS_F (64 * PSP)
#define AKV_F (AQS_F + 64 * HQP / 2)
#define ARI_F (AKV_F + 64 * HQP / 2)
#define ATTN_SMEM_BYTES ((ARI_F + 64) * 4)

__global__ __launch_bounds__(256, 1) void attn_h(
    const __half* __restrict__ Q, const __half* __restrict__ K, const __half* __restrict__ V,
    const float* __restrict__ mask, __half* __restrict__ AO)
{
    extern __shared__ float smf[];
    float*  Ps   = smf + APS_F;
    __half* Qs   = (__half*)(smf + AQS_F);
    __half* KVs  = (__half*)(smf + AKV_F);
    float*  rinv = smf + ARI_F;
    const uint32_t Qaddr  = smem_u32(Qs);
    const uint32_t KVaddr = smem_u32(KVs);

    const int qb = blockIdx.x;
    const int h  = blockIdx.y;
    const int b  = blockIdx.z;
    const int kvh = h >> 2;
    const int tid = threadIdx.x;
    const int lane = tid & 31;
    const int warp = tid >> 5;
    const int lr = lane >> 2;
    const int lc = lane & 3;

    int kblk[8]; bool kvalid[8];
#pragma unroll
    for (int w = 0; w < 4; w++) {
        int jb = qb - 3 + w;
        kblk[w] = jb < 0 ? 0 : jb;
        kvalid[w] = (jb >= 0);
    }
    {
        int start = qb - 32; if (start < 0) start = 0;
        int cnt = (qb > start) ? ((qb - start + 3) >> 2) : 0;
        int first = (cnt > 4) ? (cnt - 4) : 0;
        int sz = (cnt < 4) ? cnt : 4;
        int s0 = 4 - sz;
#pragma unroll
        for (int g = 0; g < 4; g++) {
            if (g < s0) { kblk[4 + g] = 0; kvalid[4 + g] = false; }
            else        { kblk[4 + g] = start + 4 * (first + g - s0); kvalid[4 + g] = true; }
        }
    }

    uint4 kreg[4];
    {
        const __half* Qsrc = Q + (size_t)(b * 4096 + qb * 64) * 2048 + h * 128;
#pragma unroll
        for (int it = 0; it < 4; it++) {
            int f = tid + it * 256;
            int row = f >> 4, c = f & 15;
            *(uint4*)(Qs + row * HQP + c * 8) = *(const uint4*)(Qsrc + (size_t)row * 2048 + c * 8);
        }
        const __half* Ksrc = K + (size_t)(b * 4096 + kblk[0] * 64) * 512 + kvh * 128;
#pragma unroll
        for (int it = 0; it < 4; it++) {
            int f = tid + it * 256;
            kreg[it] = *(const uint4*)(Ksrc + (size_t)(f >> 4) * 512 + (f & 15) * 8);
        }
    }
    __syncthreads();

    const int wm16 = (warp >> 1) * 16;
    const int wn32 = (warp & 1) * 32;
    const int aRow = wm16 + (lane & 15);
    const int aKoff = (lane >> 4) * 8;
    const int bRow = (lane & 7) + ((lane >> 4) & 1) * 8;
    const int bKoff = ((lane >> 3) & 1) * 8;

    for (int s = 0; s < 8; s++) {
#pragma unroll
        for (int it = 0; it < 4; it++) {
            int f = tid + it * 256;
            *(uint4*)(KVs + (f >> 4) * HQP + (f & 15) * 8) = kreg[it];
        }
        __syncthreads();
        {
            const __half* src = (s < 7)
                ? K + (size_t)(b * 4096 + kblk[s + 1] * 64) * 512 + kvh * 128
                : V + (size_t)(b * 4096 + kblk[0] * 64) * 512 + kvh * 128;
#pragma unroll
            for (int it = 0; it < 4; it++) {
                int f = tid + it * 256;
                kreg[it] = *(const uint4*)(src + (size_t)(f >> 4) * 512 + (f & 15) * 8);
            }
        }

        float acc[4][4];
#pragma unroll
        for (int nt = 0; nt < 4; nt++)
#pragma unroll
            for (int i = 0; i < 4; i++) acc[nt][i] = 0.f;

#pragma unroll
        for (int kk = 0; kk < 8; kk++) {
            uint32_t a[4];
            ldsm4(a, Qaddr + (aRow * HQP + kk * 16 + aKoff) * 2);
            uint32_t br[2][4];
#pragma unroll
            for (int nt2 = 0; nt2 < 2; nt2++)
                ldsm4(br[nt2], KVaddr + ((wn32 + nt2 * 16 + bRow) * HQP + kk * 16 + bKoff) * 2);
#pragma unroll
            for (int nt = 0; nt < 4; nt++)
                mma_f16(acc[nt], a, br[nt >> 1][(nt & 1) * 2], br[nt >> 1][(nt & 1) * 2 + 1]);
        }

        const int r0 = wm16 + lr;
        if (kvalid[s]) {
            const float* mrow = mask + (size_t)b * 4096 + kblk[s] * 64;
            const bool cz = (s == 3);
#pragma unroll
            for (int nt = 0; nt < 4; nt++) {
                const int c = wn32 + nt * 8 + 2 * lc;
                const float mv0 = (1.0f - __ldg(mrow + c)) * NEGV;
                const float mv1 = (1.0f - __ldg(mrow + c + 1)) * NEGV;
                float v0 = acc[nt][0] * SCALEV + mv0;
                float v1 = acc[nt][1] * SCALEV + mv1;
                float v2 = acc[nt][2] * SCALEV + mv0;
                float v3 = acc[nt][3] * SCALEV + mv1;
                if (cz) {
                    if (c     > r0)     v0 += NEGV;
                    if (c + 1 > r0)     v1 += NEGV;
                    if (c     > r0 + 8) v2 += NEGV;
                    if (c + 1 > r0 + 8) v3 += NEGV;
                }
                *(float2*)(Ps + (size_t)r0 * PSP + s * 64 + c)       = make_float2(v0, v1);
                *(float2*)(Ps + (size_t)(r0 + 8) * PSP + s * 64 + c) = make_float2(v2, v3);
            }
        } else {
#pragma unroll
            for (int nt = 0; nt < 4; nt++) {
                const int c = wn32 + nt * 8 + 2 * lc;
                *(float2*)(Ps + (size_t)r0 * PSP + s * 64 + c)       = make_float2(NEGV, NEGV);
                *(float2*)(Ps + (size_t)(r0 + 8) * PSP + s * 64 + c) = make_float2(NEGV, NEGV);
            }
        }
        __syncthreads();
    }

    {
        const int row = tid >> 2, q = tid & 3;
        float* pr = Ps + (size_t)row * PSP;
        float m = -3.4e38f;
#pragma unroll 8
        for (int c = q; c < 512; c += 4) m = fmaxf(m, pr[c]);
        m = fmaxf(m, __shfl_xor_sync(0xffffffffu, m, 1));
        m = fmaxf(m, __shfl_xor_sync(0xffffffffu, m, 2));
        float ssum = 0.f;
#pragma unroll 8
        for (int c = q; c < 512; c += 4) {
            float e = __expf(pr[c] - m);
            ssum += e;
            pr[c] = e;
        }
        ssum += __shfl_xor_sync(0xffffffffu, ssum, 1);
        ssum += __shfl_xor_sync(0xffffffffu, ssum, 2);
        if (q == 0) rinv[row] = 1.0f / ssum;
    }
    __syncthreads();

    float oacc[4][2][4];
#pragma unroll
    for (int mt = 0; mt < 4; mt++)
#pragma unroll
        for (int nt = 0; nt < 2; nt++)
#pragma unroll
            for (int i = 0; i < 4; i++) oacc[mt][nt][i] = 0.f;

    const int w16 = warp * 16;
    const int vKrow = (lane & 7) + ((lane >> 3) & 1) * 8;
    const int vDoff = w16 + ((lane >> 4) & 1) * 8;

    for (int s = 0; s < 8; s++) {
#pragma unroll
        for (int it = 0; it < 4; it++) {
            int f = tid + it * 256;
            *(uint4*)(KVs + (f >> 4) * HQP + (f & 15) * 8) = kreg[it];
        }
        __syncthreads();
        if (s < 7) {
            const __half* Vsrc = V + (size_t)(b * 4096 + kblk[s + 1] * 64) * 512 + kvh * 128;
#pragma unroll
            for (int it = 0; it < 4; it++) {
                int f = tid + it * 256;
                kreg[it] = *(const uint4*)(Vsrc + (size_t)(f >> 4) * 512 + (f & 15) * 8);
            }
        }

#pragma unroll
        for (int kk = 0; kk < 4; kk++) {
            uint32_t bv[4];
            ldsm4t(bv, KVaddr + ((kk * 16 + vKrow) * HQP + vDoff) * 2);
            const int kb = s * 64 + kk * 16 + 2 * lc;
#pragma unroll
            for (int mt = 0; mt < 4; mt++) {
                const int r = mt * 16 + lr;
                float2 f0 = *(float2*)(Ps + (size_t)r * PSP + kb);
                float2 f1 = *(float2*)(Ps + (size_t)(r + 8) * PSP + kb);
                float2 f2 = *(float2*)(Ps + (size_t)r * PSP + kb + 8);
                float2 f3 = *(float2*)(Ps + (size_t)(r + 8) * PSP + kb + 8);
                uint32_t a[4] = { packh2(f0.x, f0.y), packh2(f1.x, f1.y),
                                  packh2(f2.x, f2.y), packh2(f3.x, f3.y) };
                mma_f16(oacc[mt][0], a, bv[0], bv[1]);
                mma_f16(oacc[mt][1], a, bv[2], bv[3]);
            }
        }
        __syncthreads();
    }

    __half* aop = AO + (size_t)(b * 4096 + qb * 64) * 2048 + h * 128 + w16;
#pragma unroll
    for (int mt = 0; mt < 4; mt++) {
        const int r = mt * 16 + lr;
        const float ri0 = rinv[r], ri1 = rinv[r + 8];
#pragma unroll
        for (int nt = 0; nt < 2; nt++) {
            const int c = nt * 8 + 2 * lc;
            *(uint32_t*)(aop + (size_t)r * 2048 + c) =
                packh2(oacc[mt][nt][0] * ri0, oacc[mt][nt][1] * ri0);
            *(uint32_t*)(aop + (size_t)(r + 8) * 2048 + c) =
                packh2(oacc[mt][nt][2] * ri1, oacc[mt][nt][3] * ri1);
        }
    }
}

// ---------------------------------------------------------------------------
extern "C" void kernel_launch(void* const* d_in, const int* in_sizes, int n_in,
                              void* d_out, int out_size)
{
    const float* hidden = (const float*)d_in[0];
    const float* cosp   = (const float*)d_in[1];
    const float* sinp   = (const float*)d_in[2];
    const float* maskp  = (const float*)d_in[3];
    const float* Wq     = (const float*)d_in[4];
    const float* Wk     = (const float*)d_in[5];
    const float* Wv     = (const float*)d_in[6];
    const float* Wo     = (const float*)d_in[7];
    float* out = (float*)d_out;

    float *Qp, *Kp;
    __half *Qh, *Kh, *Vh, *AOh, *Xh, *WqT, *WkT, *WvT, *WoT;
    cudaGetSymbolAddress((void**)&Qp, g_Q);
    cudaGetSymbolAddress((void**)&Kp, g_K);
    cudaGetSymbolAddress((void**)&Qh, g_Qh);
    cudaGetSymbolAddress((void**)&Kh, g_Kh);
    cudaGetSymbolAddress((void**)&Vh, g_Vh);
    cudaGetSymbolAddress((void**)&AOh, g_AOh);
    cudaGetSymbolAddress((void**)&Xh, g_Xh);
    cudaGetSymbolAddress((void**)&WqT, g_WqT);
    cudaGetSymbolAddress((void**)&WkT, g_WkT);
    cudaGetSymbolAddress((void**)&WvT, g_WvT);
    cudaGetSymbolAddress((void**)&WoT, g_WoT);

    cudaFuncSetAttribute(attn_h, cudaFuncAttributeMaxDynamicSharedMemorySize,
                         ATTN_SMEM_BYTES);
    cudaFuncSetAttribute(gemm_h<false>, cudaFuncAttributeMaxDynamicSharedMemorySize,
                         GSMH_BYTES);
    cudaFuncSetAttribute(gemm_h<true>, cudaFuncAttributeMaxDynamicSharedMemorySize,
                         GSMH_BYTES);

    // prep: hidden -> half, transpose weights -> half
    const int n8 = 2 * 4096 * 2048 / 8;
    round_half<<<(n8 + 255) / 256, 256>>>(hidden, Xh, n8);
    transpose_half<<<dim3(2048 / 32, 2048 / 32), dim3(32, 8)>>>(Wq, WqT, 2048, 2048);
    transpose_half<<<dim3(512 / 32, 2048 / 32), dim3(32, 8)>>>(Wk, WkT, 2048, 512);
    transpose_half<<<dim3(512 / 32, 2048 / 32), dim3(32, 8)>>>(Wv, WvT, 2048, 512);
    transpose_half<<<dim3(2048 / 32, 2048 / 32), dim3(32, 8)>>>(Wo, WoT, 2048, 2048);

    // projections (fp16 HMMA, 128-thread CTAs): Q,K -> fp32 (rope), V -> half
    gemm_h<false><<<dim3(16, 64), 128, GSMH_BYTES>>>(Xh, WqT, Qp, 8192, 2048, 2048);
    gemm_h<false><<<dim3(4, 64), 128, GSMH_BYTES>>>(Xh, WkT, Kp, 8192, 512, 2048);
    gemm_h<true><<<dim3(4, 64), 128, GSMH_BYTES>>>(Xh, WvT, Vh, 8192, 512, 2048);

    // rope: fp32 in -> fp16 out
    rope_half<<<8192, dim3(64, 16)>>>(Qp, Qh, cosp, sinp, 16);
    rope_half<<<8192, dim3(64, 4)>>>(Kp, Kh, cosp, sinp, 4);

    // fp16 tensor-core block-sparse attention
    attn_h<<<dim3(64, 16, 2), 256, ATTN_SMEM_BYTES>>>(Qh, Kh, Vh, maskp, AOh);

    // output projection (fp16 HMMA, fp32 out)
    gemm_h<false><<<dim3(16, 64), 128, GSMH_BYTES>>>(AOh, WoT, out, 8192, 2048, 2048);
}

// round 12
// speedup vs baseline: 6.4281x; 1.0411x over previous
#include <cuda_runtime.h>
#include <cuda_fp16.h>
#include <math.h>
#include <stdint.h>

// B=2, S=4096, HID=2048, H=16, KV=4, D=128, BS=64, L=4, G=4, STRIDE=4, WTOK=2048
#define NEGV (-1000000000.0f)
#define SCALEV 0.08838834764831845f   // 1/sqrt(128)

// ---------------- scratch (__device__ globals; allocation-free rule) -------
// Q/K stored in PERMUTED-d layout within each head: p=2j <-> d=j, p=2j+1 <-> d=j+64.
// QK^T is invariant (same perm on both sides); V/AO are in natural layout.
__device__ __align__(1024) __half g_Qh [2 * 4096 * 2048];   // fp16 Q (rope applied, permuted)
__device__ __align__(1024) __half g_Kh [2 * 4096 * 512];    // fp16 K (rope applied, permuted)
__device__ __align__(1024) __half g_Vh [2 * 4096 * 512];    // fp16 V
__device__ __align__(1024) __half g_AOh[2 * 4096 * 2048];   // fp16 attention out
__device__ __align__(1024) __half g_Xh [2 * 4096 * 2048];   // fp16 hidden
__device__ __align__(1024) __half g_WqT[2048 * 2048];       // permuted cols
__device__ __align__(1024) __half g_WkT[512 * 2048];        // permuted cols
__device__ __align__(1024) __half g_WvT[512 * 2048];
__device__ __align__(1024) __half g_WoT[2048 * 2048];

// ---------------- helpers ---------------------------------------------------
__device__ __forceinline__ uint32_t smem_u32(const void* p) {
    uint32_t a;
    asm("{ .reg .u64 t; cvta.to.shared.u64 t, %1; cvt.u32.u64 %0, t; }" : "=r"(a) : "l"(p));
    return a;
}
#define CP_ASYNC16(sm, gm) \
    asm volatile("cp.async.cg.shared.global [%0], [%1], 16;" :: "r"(sm), "l"(gm) : "memory")
#define CP_COMMIT() asm volatile("cp.async.commit_group;" ::: "memory")
#define CP_WAIT0()  asm volatile("cp.async.wait_group 0;" ::: "memory")
#define CP_WAIT1()  asm volatile("cp.async.wait_group 1;" ::: "memory")
#define CP_WAIT2()  asm volatile("cp.async.wait_group 2;" ::: "memory")

__device__ __forceinline__ void mma_f16(float c[4], const uint32_t a[4], uint32_t b0, uint32_t b1) {
    asm volatile(
        "mma.sync.aligned.m16n8k16.row.col.f32.f16.f16.f32 "
        "{%0,%1,%2,%3}, {%4,%5,%6,%7}, {%8,%9}, {%0,%1,%2,%3};"
        : "+f"(c[0]), "+f"(c[1]), "+f"(c[2]), "+f"(c[3])
        : "r"(a[0]), "r"(a[1]), "r"(a[2]), "r"(a[3]), "r"(b0), "r"(b1));
}
__device__ __forceinline__ void ldsm4(uint32_t r[4], uint32_t addr) {
    asm volatile("ldmatrix.sync.aligned.m8n8.x4.shared.b16 {%0,%1,%2,%3}, [%4];"
                 : "=r"(r[0]), "=r"(r[1]), "=r"(r[2]), "=r"(r[3]) : "r"(addr));
}
__device__ __forceinline__ void ldsm4t(uint32_t r[4], uint32_t addr) {
    asm volatile("ldmatrix.sync.aligned.m8n8.x4.trans.shared.b16 {%0,%1,%2,%3}, [%4];"
                 : "=r"(r[0]), "=r"(r[1]), "=r"(r[2]), "=r"(r[3]) : "r"(addr));
}
__device__ __forceinline__ uint32_t packh2(float x, float y) {
    __half2 h = __floats2half2_rn(x, y);
    return *(uint32_t*)&h;
}

// ---------------------------------------------------------------------------
// GEMM core config: 128x128 CTA tile, 4 warps, warp tile 64x64, BK=32,
// 4-stage cp.async. Pitch 40 halves (80B): conflict-free ldmatrix.
// ---------------------------------------------------------------------------
#define HP2  40
#define STGH (128 * HP2)
#define GSMH_BYTES (8 * STGH * 2)             // 81920 B

#define GLOADH(buf, k0)                                                                \
    do {                                                                               \
        _Pragma("unroll")                                                              \
        for (int it = 0; it < 4; it++) {                                               \
            const int row = ldrow + it * 32;                                           \
            const uint32_t so = (uint32_t)(((buf) * STGH + row * HP2 + ldc * 8) * 2);  \
            CP_ASYNC16(smbA + so, A  + (size_t)(crow0 + row) * K + (k0) + ldc * 8);    \
            CP_ASYNC16(smbB + so, Bt + (size_t)(ccol0 + row) * K + (k0) + ldc * 8);    \
        }                                                                              \
    } while (0)

#define GEMM_MAIN(T)                                                                   \
    GLOADH(0, 0);  CP_COMMIT();                                                        \
    GLOADH(1, 32); CP_COMMIT();                                                        \
    GLOADH(2, 64); CP_COMMIT();                                                        \
    for (int t = 0; t < (T); t++) {                                                    \
        const int rem = (T) - 1 - t;                                                   \
        if (rem >= 2) CP_WAIT2(); else if (rem == 1) CP_WAIT1(); else CP_WAIT0();      \
        __syncthreads();                                                               \
        if (t + 3 < (T)) { GLOADH((t + 3) & 3, (t + 3) << 5); CP_COMMIT(); }           \
        const int buf = t & 3;                                                         \
        const uint32_t Ab = smbA + buf * STGH * 2;                                     \
        const uint32_t Bb = smbB + buf * STGH * 2;                                     \
        _Pragma("unroll")                                                              \
        for (int kk = 0; kk < 2; kk++) {                                               \
            uint32_t a[4][4];                                                          \
            _Pragma("unroll")                                                          \
            for (int mt = 0; mt < 4; mt++)                                             \
                ldsm4(a[mt], Ab + ((aRowBase + mt * 16) * HP2 + kk * 16 + aKoff) * 2); \
            uint32_t br[4][4];                                                         \
            _Pragma("unroll")                                                          \
            for (int g = 0; g < 4; g++)                                                \
                ldsm4(br[g], Bb + ((bRowBase + g * 16) * HP2 + kk * 16 + bKoff) * 2);  \
            _Pragma("unroll")                                                          \
            for (int mt = 0; mt < 4; mt++)                                             \
                _Pragma("unroll")                                                      \
                for (int nt = 0; nt < 8; nt++)                                         \
                    mma_f16(acc[mt][nt], a[mt], br[nt >> 1][(nt & 1) * 2],             \
                            br[nt >> 1][(nt & 1) * 2 + 1]);                            \
        }                                                                              \
    }

// ---------------------------------------------------------------------------
// Fused QKV projection GEMM + RoPE epilogue (Q,K regions; V plain).
// grid.x: 0-15 Q | 16-19 K | 20-23 V. grid.y: 64 row tiles. 128 threads.
// Q/K outputs are rope'd and written in the permuted-d layout (matches WqT/WkT).
// ---------------------------------------------------------------------------
__global__ __launch_bounds__(128, 2) void gemm_qkv(
    const __half* __restrict__ A,
    const __half* __restrict__ WqT_, const __half* __restrict__ WkT_,
    const __half* __restrict__ WvT_,
    __half* __restrict__ Qh, __half* __restrict__ Kh, __half* __restrict__ Vh,
    const float* __restrict__ cosp, const float* __restrict__ sinp)
{
    extern __shared__ __half smh[];
    const uint32_t smbA = smem_u32(smh);
    const uint32_t smbB = smbA + 4 * STGH * 2;

    const int bx = blockIdx.x;
    const __half* Bt;
    __half* C;
    int Nc, ccol0;
    bool rope;
    if (bx < 16)      { Bt = WqT_; C = Qh; Nc = 2048; ccol0 = bx * 128;        rope = true;  }
    else if (bx < 20) { Bt = WkT_; C = Kh; Nc = 512;  ccol0 = (bx - 16) * 128; rope = true;  }
    else              { Bt = WvT_; C = Vh; Nc = 512;  ccol0 = (bx - 20) * 128; rope = false; }
    const int K = 2048;

    const int tid  = threadIdx.x;
    const int lane = tid & 31;
    const int warp = tid >> 5;
    const int wm = warp & 1;
    const int wn = warp >> 1;
    const int lr = lane >> 2;
    const int lc = lane & 3;
    const int crow0 = blockIdx.y * 128;

    const int ldrow = tid >> 2;
    const int ldc   = tid & 3;

    float acc[4][8][4];
#pragma unroll
    for (int mt = 0; mt < 4; mt++)
#pragma unroll
        for (int nt = 0; nt < 8; nt++)
#pragma unroll
            for (int i = 0; i < 4; i++) acc[mt][nt][i] = 0.f;

    const int aRowBase = wm * 64 + (lane & 15);
    const int aKoff    = (lane >> 4) * 8;
    const int bRowBase = wn * 64 + (lane & 7) + ((lane >> 4) & 1) * 8;
    const int bKoff    = ((lane >> 3) & 1) * 8;

    GEMM_MAIN(64)   // K=2048 / 32

    if (rope) {
#pragma unroll
        for (int mt = 0; mt < 4; mt++) {
            const int r0 = crow0 + wm * 64 + mt * 16 + lr;
#pragma unroll
            for (int nt = 0; nt < 8; nt++) {
                const int col = ccol0 + wn * 64 + nt * 8 + 2 * lc;   // permuted p (even)
                const int d = (col & 127) >> 1;                      // orig d of acc[...][0]
                // row r0
                {
                    const float c1 = __ldg(cosp + (size_t)r0 * 128 + d);
                    const float s1 = __ldg(sinp + (size_t)r0 * 128 + d);
                    const float c2 = __ldg(cosp + (size_t)r0 * 128 + d + 64);
                    const float s2 = __ldg(sinp + (size_t)r0 * 128 + d + 64);
                    const float a0 = acc[mt][nt][0], a1 = acc[mt][nt][1];
                    *(uint32_t*)(C + (size_t)r0 * Nc + col) =
                        packh2(a0 * c1 - a1 * s1, a1 * c2 + a0 * s2);
                }
                // row r0+8
                {
                    const int r1 = r0 + 8;
                    const float c1 = __ldg(cosp + (size_t)r1 * 128 + d);
                    const float s1 = __ldg(sinp + (size_t)r1 * 128 + d);
                    const float c2 = __ldg(cosp + (size_t)r1 * 128 + d + 64);
                    const float s2 = __ldg(sinp + (size_t)r1 * 128 + d + 64);
                    const float a0 = acc[mt][nt][2], a1 = acc[mt][nt][3];
                    *(uint32_t*)(C + (size_t)r1 * Nc + col) =
                        packh2(a0 * c1 - a1 * s1, a1 * c2 + a0 * s2);
                }
            }
        }
    } else {
#pragma unroll
        for (int mt = 0; mt < 4; mt++) {
            const int row = crow0 + wm * 64 + mt * 16 + lr;
#pragma unroll
            for (int nt = 0; nt < 8; nt++) {
                const int col = ccol0 + wn * 64 + nt * 8 + 2 * lc;
                *(uint32_t*)(C + (size_t)row * Nc + col)       = packh2(acc[mt][nt][0], acc[mt][nt][1]);
                *(uint32_t*)(C + (size_t)(row + 8) * Nc + col) = packh2(acc[mt][nt][2], acc[mt][nt][3]);
            }
        }
    }
}

// ---------------------------------------------------------------------------
// Plain GEMM for the output projection (fp32 out).
// ---------------------------------------------------------------------------
__global__ __launch_bounds__(128, 2) void gemm_wo(
    const __half* __restrict__ A, const __half* __restrict__ Bt, float* __restrict__ C,
    int M, int N, int K)
{
    extern __shared__ __half smh[];
    const uint32_t smbA = smem_u32(smh);
    const uint32_t smbB = smbA + 4 * STGH * 2;

    const int tid  = threadIdx.x;
    const int lane = tid & 31;
    const int warp = tid >> 5;
    const int wm = warp & 1;
    const int wn = warp >> 1;
    const int lr = lane >> 2;
    const int lc = lane & 3;
    const int crow0 = blockIdx.y * 128;
    const int ccol0 = blockIdx.x * 128;

    const int ldrow = tid >> 2;
    const int ldc   = tid & 3;

    float acc[4][8][4];
#pragma unroll
    for (int mt = 0; mt < 4; mt++)
#pragma unroll
        for (int nt = 0; nt < 8; nt++)
#pragma unroll
            for (int i = 0; i < 4; i++) acc[mt][nt][i] = 0.f;

    const int aRowBase = wm * 64 + (lane & 15);
    const int aKoff    = (lane >> 4) * 8;
    const int bRowBase = wn * 64 + (lane & 7) + ((lane >> 4) & 1) * 8;
    const int bKoff    = ((lane >> 3) & 1) * 8;

    const int T = K >> 5;
    GEMM_MAIN(T)

#pragma unroll
    for (int mt = 0; mt < 4; mt++) {
        const int row = crow0 + wm * 64 + mt * 16 + lr;
#pragma unroll
        for (int nt = 0; nt < 8; nt++) {
            const int col = ccol0 + wn * 64 + nt * 8 + 2 * lc;
            *(float2*)(C + (size_t)row * N + col)       = make_float2(acc[mt][nt][0], acc[mt][nt][1]);
            *(float2*)(C + (size_t)(row + 8) * N + col) = make_float2(acc[mt][nt][2], acc[mt][nt][3]);
        }
    }
}

// ---------------------------------------------------------------------------
// prep kernels
// ---------------------------------------------------------------------------
__global__ void round_half(const float* __restrict__ src, __half* __restrict__ dst, int n8) {
    int i = blockIdx.x * blockDim.x + threadIdx.x;
    if (i < n8) {
        float4 v0 = ((const float4*)src)[2 * i];
        float4 v1 = ((const float4*)src)[2 * i + 1];
        uint4 o;
        o.x = packh2(v0.x, v0.y); o.y = packh2(v0.z, v0.w);
        o.z = packh2(v1.x, v1.y); o.w = packh2(v1.z, v1.w);
        ((uint4*)dst)[i] = o;
    }
}
// W [K,N] fp32 -> Wt [N,K] half (natural layout).
__global__ void transpose_half(const float* __restrict__ W, __half* __restrict__ Wt,
                               int K, int N) {
    __shared__ float t[32][33];
    const int n0 = blockIdx.x * 32, k0 = blockIdx.y * 32;
    const int x = threadIdx.x, y = threadIdx.y;
#pragma unroll
    for (int j = 0; j < 32; j += 8)
        t[y + j][x] = W[(size_t)(k0 + y + j) * N + n0 + x];
    __syncthreads();
#pragma unroll
    for (int j = 0; j < 32; j += 8)
        Wt[(size_t)(n0 + y + j) * K + k0 + x] = __float2half_rn(t[x][y + j]);
}
// W [K,N] fp32 -> Wt [N',K] half with per-head column permutation:
// within each 128-col head, d<64 -> p=2d ; d>=64 -> p=2(d-64)+1.
__global__ void transpose_half_perm(const float* __restrict__ W, __half* __restrict__ Wt,
                                    int K, int N) {
    __shared__ float t[32][33];
    const int n0 = blockIdx.x * 32, k0 = blockIdx.y * 32;
    const int x = threadIdx.x, y = threadIdx.y;
#pragma unroll
    for (int j = 0; j < 32; j += 8)
        t[y + j][x] = W[(size_t)(k0 + y + j) * N + n0 + x];
    __syncthreads();
#pragma unroll
    for (int j = 0; j < 32; j += 8) {
        const int n = n0 + y + j;
        const int d = n & 127;
        const int p = (d < 64) ? (2 * d) : (2 * (d - 64) + 1);
        const int npr = (n & ~127) | p;
        Wt[(size_t)npr * K + k0 + x] = __float2half_rn(t[x][y + j]);
    }
}

// ---------------------------------------------------------------------------
// fp16 tensor-core block-sparse attention (unchanged from R9/R10 — passing).
// Q/K arrive in permuted-d layout; QK^T is invariant to that.
// ---------------------------------------------------------------------------
#define PSP   520
#define HQP   136
#define APS_F 0
#define AQS_F (64 * PSP)
#define AKV_F (AQS_F + 64 * HQP / 2)
#define ARI_F (AKV_F + 64 * HQP / 2)
#define ATTN_SMEM_BYTES ((ARI_F + 64) * 4)

__global__ __launch_bounds__(256, 1) void attn_h(
    const __half* __restrict__ Q, const __half* __restrict__ K, const __half* __restrict__ V,
    const float* __restrict__ mask, __half* __restrict__ AO)
{
    extern __shared__ float smf[];
    float*  Ps   = smf + APS_F;
    __half* Qs   = (__half*)(smf + AQS_F);
    __half* KVs  = (__half*)(smf + AKV_F);
    float*  rinv = smf + ARI_F;
    const uint32_t Qaddr  = smem_u32(Qs);
    const uint32_t KVaddr = smem_u32(KVs);

    const int qb = blockIdx.x;
    const int h  = blockIdx.y;
    const int b  = blockIdx.z;
    const int kvh = h >> 2;
    const int tid = threadIdx.x;
    const int lane = tid & 31;
    const int warp = tid >> 5;
    const int lr = lane >> 2;
    const int lc = lane & 3;

    int kblk[8]; bool kvalid[8];
#pragma unroll
    for (int w = 0; w < 4; w++) {
        int jb = qb - 3 + w;
        kblk[w] = jb < 0 ? 0 : jb;
        kvalid[w] = (jb >= 0);
    }
    {
        int start = qb - 32; if (start < 0) start = 0;
        int cnt = (qb > start) ? ((qb - start + 3) >> 2) : 0;
        int first = (cnt > 4) ? (cnt - 4) : 0;
        int sz = (cnt < 4) ? cnt : 4;
        int s0 = 4 - sz;
#pragma unroll
        for (int g = 0; g < 4; g++) {
            if (g < s0) { kblk[4 + g] = 0; kvalid[4 + g] = false; }
            else        { kblk[4 + g] = start + 4 * (first + g - s0); kvalid[4 + g] = true; }
        }
    }

    uint4 kreg[4];
    {
        const __half* Qsrc = Q + (size_t)(b * 4096 + qb * 64) * 2048 + h * 128;
#pragma unroll
        for (int it = 0; it < 4; it++) {
            int f = tid + it * 256;
            int row = f >> 4, c = f & 15;
            *(uint4*)(Qs + row * HQP + c * 8) = *(const uint4*)(Qsrc + (size_t)row * 2048 + c * 8);
        }
        const __half* Ksrc = K + (size_t)(b * 4096 + kblk[0] * 64) * 512 + kvh * 128;
#pragma unroll
        for (int it = 0; it < 4; it++) {
            int f = tid + it * 256;
            kreg[it] = *(const uint4*)(Ksrc + (size_t)(f >> 4) * 512 + (f & 15) * 8);
        }
    }
    __syncthreads();

    const int wm16 = (warp >> 1) * 16;
    const int wn32 = (warp & 1) * 32;
    const int aRow = wm16 + (lane & 15);
    const int aKoff = (lane >> 4) * 8;
    const int bRow = (lane & 7) + ((lane >> 4) & 1) * 8;
    const int bKoff = ((lane >> 3) & 1) * 8;

    for (int s = 0; s < 8; s++) {
#pragma unroll
        for (int it = 0; it < 4; it++) {
            int f = tid + it * 256;
            *(uint4*)(KVs + (f >> 4) * HQP + (f & 15) * 8) = kreg[it];
        }
        __syncthreads();
        {
            const __half* src = (s < 7)
                ? K + (size_t)(b * 4096 + kblk[s + 1] * 64) * 512 + kvh * 128
                : V + (size_t)(b * 4096 + kblk[0] * 64) * 512 + kvh * 128;
#pragma unroll
            for (int it = 0; it < 4; it++) {
                int f = tid + it * 256;
                kreg[it] = *(const uint4*)(src + (size_t)(f >> 4) * 512 + (f & 15) * 8);
            }
        }

        float acc[4][4];
#pragma unroll
        for (int nt = 0; nt < 4; nt++)
#pragma unroll
            for (int i = 0; i < 4; i++) acc[nt][i] = 0.f;

#pragma unroll
        for (int kk = 0; kk < 8; kk++) {
            uint32_t a[4];
            ldsm4(a, Qaddr + (aRow * HQP + kk * 16 + aKoff) * 2);
            uint32_t br[2][4];
#pragma unroll
            for (int nt2 = 0; nt2 < 2; nt2++)
                ldsm4(br[nt2], KVaddr + ((wn32 + nt2 * 16 + bRow) * HQP + kk * 16 + bKoff) * 2);
#pragma unroll
            for (int nt = 0; nt < 4; nt++)
                mma_f16(acc[nt], a, br[nt >> 1][(nt & 1) * 2], br[nt >> 1][(nt & 1) * 2 + 1]);
        }

        const int r0 = wm16 + lr;
        if (kvalid[s]) {
            const float* mrow = mask + (size_t)b * 4096 + kblk[s] * 64;
            const bool cz = (s == 3);
#pragma unroll
            for (int nt = 0; nt < 4; nt++) {
                const int c = wn32 + nt * 8 + 2 * lc;
                const float mv0 = (1.0f - __ldg(mrow + c)) * NEGV;
                const float mv1 = (1.0f - __ldg(mrow + c + 1)) * NEGV;
                float v0 = acc[nt][0] * SCALEV + mv0;
                float v1 = acc[nt][1] * SCALEV + mv1;
                float v2 = acc[nt][2] * SCALEV + mv0;
                float v3 = acc[nt][3] * SCALEV + mv1;
                if (cz) {
                    if (c     > r0)     v0 += NEGV;
                    if (c + 1 > r0)     v1 += NEGV;
                    if (c     > r0 + 8) v2 += NEGV;
                    if (c + 1 > r0 + 8) v3 += NEGV;
                }
                *(float2*)(Ps + (size_t)r0 * PSP + s * 64 + c)       = make_float2(v0, v1);
                *(float2*)(Ps + (size_t)(r0 + 8) * PSP + s * 64 + c) = make_float2(v2, v3);
            }
        } else {
#pragma unroll
            for (int nt = 0; nt < 4; nt++) {
                const int c = wn32 + nt * 8 + 2 * lc;
                *(float2*)(Ps + (size_t)r0 * PSP + s * 64 + c)       = make_float2(NEGV, NEGV);
                *(float2*)(Ps + (size_t)(r0 + 8) * PSP + s * 64 + c) = make_float2(NEGV, NEGV);
            }
        }
        __syncthreads();
    }

    {
        const int row = tid >> 2, q = tid & 3;
        float* pr = Ps + (size_t)row * PSP;
        float m = -3.4e38f;
#pragma unroll 8
        for (int c = q; c < 512; c += 4) m = fmaxf(m, pr[c]);
        m = fmaxf(m, __shfl_xor_sync(0xffffffffu, m, 1));
        m = fmaxf(m, __shfl_xor_sync(0xffffffffu, m, 2));
        float ssum = 0.f;
#pragma unroll 8
        for (int c = q; c < 512; c += 4) {
            float e = __expf(pr[c] - m);
            ssum += e;
            pr[c] = e;
        }
        ssum += __shfl_xor_sync(0xffffffffu, ssum, 1);
        ssum += __shfl_xor_sync(0xffffffffu, ssum, 2);
        if (q == 0) rinv[row] = 1.0f / ssum;
    }
    __syncthreads();

    float oacc[4][2][4];
#pragma unroll
    for (int mt = 0; mt < 4; mt++)
#pragma unroll
        for (int nt = 0; nt < 2; nt++)
#pragma unroll
            for (int i = 0; i < 4; i++) oacc[mt][nt][i] = 0.f;

    const int w16 = warp * 16;
    const int vKrow = (lane & 7) + ((lane >> 3) & 1) * 8;
    const int vDoff = w16 + ((lane >> 4) & 1) * 8;

    for (int s = 0; s < 8; s++) {
#pragma unroll
        for (int it = 0; it < 4; it++) {
            int f = tid + it * 256;
            *(uint4*)(KVs + (f >> 4) * HQP + (f & 15) * 8) = kreg[it];
        }
        __syncthreads();
        if (s < 7) {
            const __half* Vsrc = V + (size_t)(b * 4096 + kblk[s + 1] * 64) * 512 + kvh * 128;
#pragma unroll
            for (int it = 0; it < 4; it++) {
                int f = tid + it * 256;
                kreg[it] = *(const uint4*)(Vsrc + (size_t)(f >> 4) * 512 + (f & 15) * 8);
            }
        }

#pragma unroll
        for (int kk = 0; kk < 4; kk++) {
            uint32_t bv[4];
            ldsm4t(bv, KVaddr + ((kk * 16 + vKrow) * HQP + vDoff) * 2);
            const int kb = s * 64 + kk * 16 + 2 * lc;
#pragma unroll
            for (int mt = 0; mt < 4; mt++) {
                const int r = mt * 16 + lr;
                float2 f0 = *(float2*)(Ps + (size_t)r * PSP + kb);
                float2 f1 = *(float2*)(Ps + (size_t)(r + 8) * PSP + kb);
                float2 f2 = *(float2*)(Ps + (size_t)r * PSP + kb + 8);
                float2 f3 = *(float2*)(Ps + (size_t)(r + 8) * PSP + kb + 8);
                uint32_t a[4] = { packh2(f0.x, f0.y), packh2(f1.x, f1.y),
                                  packh2(f2.x, f2.y), packh2(f3.x, f3.y) };
                mma_f16(oacc[mt][0], a, bv[0], bv[1]);
                mma_f16(oacc[mt][1], a, bv[2], bv[3]);
            }
        }
        __syncthreads();
    }

    __half* aop = AO + (size_t)(b * 4096 + qb * 64) * 2048 + h * 128 + w16;
#pragma unroll
    for (int mt = 0; mt < 4; mt++) {
        const int r = mt * 16 + lr;
        const float ri0 = rinv[r], ri1 = rinv[r + 8];
#pragma unroll
        for (int nt = 0; nt < 2; nt++) {
            const int c = nt * 8 + 2 * lc;
            *(uint32_t*)(aop + (size_t)r * 2048 + c) =
                packh2(oacc[mt][nt][0] * ri0, oacc[mt][nt][1] * ri0);
            *(uint32_t*)(aop + (size_t)(r + 8) * 2048 + c) =
                packh2(oacc[mt][nt][2] * ri1, oacc[mt][nt][3] * ri1);
        }
    }
}

// ---------------------------------------------------------------------------
extern "C" void kernel_launch(void* const* d_in, const int* in_sizes, int n_in,
                              void* d_out, int out_size)
{
    const float* hidden = (const float*)d_in[0];
    const float* cosp   = (const float*)d_in[1];
    const float* sinp   = (const float*)d_in[2];
    const float* maskp  = (const float*)d_in[3];
    const float* Wq     = (const float*)d_in[4];
    const float* Wk     = (const float*)d_in[5];
    const float* Wv     = (const float*)d_in[6];
    const float* Wo     = (const float*)d_in[7];
    float* out = (float*)d_out;

    __half *Qh, *Kh, *Vh, *AOh, *Xh, *WqT, *WkT, *WvT, *WoT;
    cudaGetSymbolAddress((void**)&Qh, g_Qh);
    cudaGetSymbolAddress((void**)&Kh, g_Kh);
    cudaGetSymbolAddress((void**)&Vh, g_Vh);
    cudaGetSymbolAddress((void**)&AOh, g_AOh);
    cudaGetSymbolAddress((void**)&Xh, g_Xh);
    cudaGetSymbolAddress((void**)&WqT, g_WqT);
    cudaGetSymbolAddress((void**)&WkT, g_WkT);
    cudaGetSymbolAddress((void**)&WvT, g_WvT);
    cudaGetSymbolAddress((void**)&WoT, g_WoT);

    cudaFuncSetAttribute(attn_h, cudaFuncAttributeMaxDynamicSharedMemorySize,
                         ATTN_SMEM_BYTES);
    cudaFuncSetAttribute(gemm_qkv, cudaFuncAttributeMaxDynamicSharedMemorySize,
                         GSMH_BYTES);
    cudaFuncSetAttribute(gemm_wo, cudaFuncAttributeMaxDynamicSharedMemorySize,
                         GSMH_BYTES);

    // prep: hidden -> half; weights -> transposed half (Wq/Wk with rope-pair perm)
    const int n8 = 2 * 4096 * 2048 / 8;
    round_half<<<(n8 + 255) / 256, 256>>>(hidden, Xh, n8);
    transpose_half_perm<<<dim3(2048 / 32, 2048 / 32), dim3(32, 8)>>>(Wq, WqT, 2048, 2048);
    transpose_half_perm<<<dim3(512 / 32, 2048 / 32), dim3(32, 8)>>>(Wk, WkT, 2048, 512);
    transpose_half<<<dim3(512 / 32, 2048 / 32), dim3(32, 8)>>>(Wv, WvT, 2048, 512);
    transpose_half<<<dim3(2048 / 32, 2048 / 32), dim3(32, 8)>>>(Wo, WoT, 2048, 2048);

    // fused QKV projections + RoPE (Q/K written rope'd, permuted-d, fp16)
    gemm_qkv<<<dim3(24, 64), 128, GSMH_BYTES>>>(Xh, WqT, WkT, WvT, Qh, Kh, Vh, cosp, sinp);

    // fp16 tensor-core block-sparse attention (perm-invariant QK^T)
    attn_h<<<dim3(64, 16, 2), 256, ATTN_SMEM_BYTES>>>(Qh, Kh, Vh, maskp, AOh);

    // output projection (fp16 HMMA, fp32 out)
    gemm_wo<<<dim3(16, 64), 128, GSMH_BYTES>>>(AOh, WoT, out, 8192, 2048, 2048);
}

// round 13
// speedup vs baseline: 7.7011x; 1.1980x over previous
#include <cuda_runtime.h>
#include <cuda_fp16.h>
#include <math.h>
#include <stdint.h>

// B=2, S=4096, HID=2048, H=16, KV=4, D=128, BS=64, L=4, G=4, STRIDE=4, WTOK=2048
#define NEGV (-1000000000.0f)
#define SCALEV 0.08838834764831845f   // 1/sqrt(128)

// ---------------- scratch (__device__ globals; allocation-free rule) -------
// Q/K stored in PERMUTED-d layout within each head: p=2j <-> d=j, p=2j+1 <-> d=j+64.
// QK^T is invariant (same perm on both sides); V/AO are in natural layout.
__device__ __align__(1024) __half g_Qh [2 * 4096 * 2048];
__device__ __align__(1024) __half g_Kh [2 * 4096 * 512];
__device__ __align__(1024) __half g_Vh [2 * 4096 * 512];
__device__ __align__(1024) __half g_AOh[2 * 4096 * 2048];
__device__ __align__(1024) __half g_Xh [2 * 4096 * 2048];
__device__ __align__(1024) __half g_WqT[2048 * 2048];
__device__ __align__(1024) __half g_WkT[512 * 2048];
__device__ __align__(1024) __half g_WvT[512 * 2048];
__device__ __align__(1024) __half g_WoT[2048 * 2048];

// ---------------- helpers ---------------------------------------------------
__device__ __forceinline__ uint32_t smem_u32(const void* p) {
    uint32_t a;
    asm("{ .reg .u64 t; cvta.to.shared.u64 t, %1; cvt.u32.u64 %0, t; }" : "=r"(a) : "l"(p));
    return a;
}
#define CP_ASYNC16(sm, gm) \
    asm volatile("cp.async.cg.shared.global [%0], [%1], 16;" :: "r"(sm), "l"(gm) : "memory")
#define CP_COMMIT() asm volatile("cp.async.commit_group;" ::: "memory")
#define CP_WAIT0()  asm volatile("cp.async.wait_group 0;" ::: "memory")
#define CP_WAIT1()  asm volatile("cp.async.wait_group 1;" ::: "memory")
#define CP_WAIT2()  asm volatile("cp.async.wait_group 2;" ::: "memory")

__device__ __forceinline__ void mma_f16(float c[4], const uint32_t a[4], uint32_t b0, uint32_t b1) {
    asm volatile(
        "mma.sync.aligned.m16n8k16.row.col.f32.f16.f16.f32 "
        "{%0,%1,%2,%3}, {%4,%5,%6,%7}, {%8,%9}, {%0,%1,%2,%3};"
        : "+f"(c[0]), "+f"(c[1]), "+f"(c[2]), "+f"(c[3])
        : "r"(a[0]), "r"(a[1]), "r"(a[2]), "r"(a[3]), "r"(b0), "r"(b1));
}
__device__ __forceinline__ void ldsm4(uint32_t r[4], uint32_t addr) {
    asm volatile("ldmatrix.sync.aligned.m8n8.x4.shared.b16 {%0,%1,%2,%3}, [%4];"
                 : "=r"(r[0]), "=r"(r[1]), "=r"(r[2]), "=r"(r[3]) : "r"(addr));
}
__device__ __forceinline__ void ldsm4t(uint32_t r[4], uint32_t addr) {
    asm volatile("ldmatrix.sync.aligned.m8n8.x4.trans.shared.b16 {%0,%1,%2,%3}, [%4];"
                 : "=r"(r[0]), "=r"(r[1]), "=r"(r[2]), "=r"(r[3]) : "r"(addr));
}
__device__ __forceinline__ uint32_t packh2(float x, float y) {
    __half2 h = __floats2half2_rn(x, y);
    return *(uint32_t*)&h;
}

// ---------------------------------------------------------------------------
// GEMM core config: 128x128 CTA tile, 4 warps, warp tile 64x64, BK=32,
// 4-stage cp.async. Pitch 40 halves (80B): conflict-free ldmatrix.
// ---------------------------------------------------------------------------
#define HP2  40
#define STGH (128 * HP2)
#define GSMH_BYTES (8 * STGH * 2)             // 81920 B

#define GLOADH(buf, k0)                                                                \
    do {                                                                               \
        _Pragma("unroll")                                                              \
        for (int it = 0; it < 4; it++) {                                               \
            const int row = ldrow + it * 32;                                           \
            const uint32_t so = (uint32_t)(((buf) * STGH + row * HP2 + ldc * 8) * 2);  \
            CP_ASYNC16(smbA + so, A  + (size_t)(crow0 + row) * K + (k0) + ldc * 8);    \
            CP_ASYNC16(smbB + so, Bt + (size_t)(ccol0 + row) * K + (k0) + ldc * 8);    \
        }                                                                              \
    } while (0)

#define GEMM_MAIN(T)                                                                   \
    GLOADH(0, 0);  CP_COMMIT();                                                        \
    GLOADH(1, 32); CP_COMMIT();                                                        \
    GLOADH(2, 64); CP_COMMIT();                                                        \
    for (int t = 0; t < (T); t++) {                                                    \
        const int rem = (T) - 1 - t;                                                   \
        if (rem >= 2) CP_WAIT2(); else if (rem == 1) CP_WAIT1(); else CP_WAIT0();      \
        __syncthreads();                                                               \
        if (t + 3 < (T)) { GLOADH((t + 3) & 3, (t + 3) << 5); CP_COMMIT(); }           \
        const int buf = t & 3;                                                         \
        const uint32_t Ab = smbA + buf * STGH * 2;                                     \
        const uint32_t Bb = smbB + buf * STGH * 2;                                     \
        _Pragma("unroll")                                                              \
        for (int kk = 0; kk < 2; kk++) {                                               \
            uint32_t a[4][4];                                                          \
            _Pragma("unroll")                                                          \
            for (int mt = 0; mt < 4; mt++)                                             \
                ldsm4(a[mt], Ab + ((aRowBase + mt * 16) * HP2 + kk * 16 + aKoff) * 2); \
            uint32_t br[4][4];                                                         \
            _Pragma("unroll")                                                          \
            for (int g = 0; g < 4; g++)                                                \
                ldsm4(br[g], Bb + ((bRowBase + g * 16) * HP2 + kk * 16 + bKoff) * 2);  \
            _Pragma("unroll")                                                          \
            for (int mt = 0; mt < 4; mt++)                                             \
                _Pragma("unroll")                                                      \
                for (int nt = 0; nt < 8; nt++)                                         \
                    mma_f16(acc[mt][nt], a[mt], br[nt >> 1][(nt & 1) * 2],             \
                            br[nt >> 1][(nt & 1) * 2 + 1]);                            \
        }                                                                              \
    }

// ---------------------------------------------------------------------------
// Fused QKV projection GEMM + RoPE epilogue (Q,K regions; V plain).
// grid.x: 0-15 Q | 16-19 K | 20-23 V. grid.y: 64 row tiles. 128 threads.
// ---------------------------------------------------------------------------
__global__ __launch_bounds__(128, 2) void gemm_qkv(
    const __half* __restrict__ A,
    const __half* __restrict__ WqT_, const __half* __restrict__ WkT_,
    const __half* __restrict__ WvT_,
    __half* __restrict__ Qh, __half* __restrict__ Kh, __half* __restrict__ Vh,
    const float* __restrict__ cosp, const float* __restrict__ sinp)
{
    extern __shared__ __half smh[];
    const uint32_t smbA = smem_u32(smh);
    const uint32_t smbB = smbA + 4 * STGH * 2;

    const int bx = blockIdx.x;
    const __half* Bt;
    __half* C;
    int Nc, ccol0;
    bool rope;
    if (bx < 16)      { Bt = WqT_; C = Qh; Nc = 2048; ccol0 = bx * 128;        rope = true;  }
    else if (bx < 20) { Bt = WkT_; C = Kh; Nc = 512;  ccol0 = (bx - 16) * 128; rope = true;  }
    else              { Bt = WvT_; C = Vh; Nc = 512;  ccol0 = (bx - 20) * 128; rope = false; }
    const int K = 2048;

    const int tid  = threadIdx.x;
    const int lane = tid & 31;
    const int warp = tid >> 5;
    const int wm = warp & 1;
    const int wn = warp >> 1;
    const int lr = lane >> 2;
    const int lc = lane & 3;
    const int crow0 = blockIdx.y * 128;

    const int ldrow = tid >> 2;
    const int ldc   = tid & 3;

    float acc[4][8][4];
#pragma unroll
    for (int mt = 0; mt < 4; mt++)
#pragma unroll
        for (int nt = 0; nt < 8; nt++)
#pragma unroll
            for (int i = 0; i < 4; i++) acc[mt][nt][i] = 0.f;

    const int aRowBase = wm * 64 + (lane & 15);
    const int aKoff    = (lane >> 4) * 8;
    const int bRowBase = wn * 64 + (lane & 7) + ((lane >> 4) & 1) * 8;
    const int bKoff    = ((lane >> 3) & 1) * 8;

    GEMM_MAIN(64)

    if (rope) {
#pragma unroll
        for (int mt = 0; mt < 4; mt++) {
            const int r0 = crow0 + wm * 64 + mt * 16 + lr;
#pragma unroll
            for (int nt = 0; nt < 8; nt++) {
                const int col = ccol0 + wn * 64 + nt * 8 + 2 * lc;
                const int d = (col & 127) >> 1;
                {
                    const float c1 = __ldg(cosp + (size_t)r0 * 128 + d);
                    const float s1 = __ldg(sinp + (size_t)r0 * 128 + d);
                    const float c2 = __ldg(cosp + (size_t)r0 * 128 + d + 64);
                    const float s2 = __ldg(sinp + (size_t)r0 * 128 + d + 64);
                    const float a0 = acc[mt][nt][0], a1 = acc[mt][nt][1];
                    *(uint32_t*)(C + (size_t)r0 * Nc + col) =
                        packh2(a0 * c1 - a1 * s1, a1 * c2 + a0 * s2);
                }
                {
                    const int r1 = r0 + 8;
                    const float c1 = __ldg(cosp + (size_t)r1 * 128 + d);
                    const float s1 = __ldg(sinp + (size_t)r1 * 128 + d);
                    const float c2 = __ldg(cosp + (size_t)r1 * 128 + d + 64);
                    const float s2 = __ldg(sinp + (size_t)r1 * 128 + d + 64);
                    const float a0 = acc[mt][nt][2], a1 = acc[mt][nt][3];
                    *(uint32_t*)(C + (size_t)r1 * Nc + col) =
                        packh2(a0 * c1 - a1 * s1, a1 * c2 + a0 * s2);
                }
            }
        }
    } else {
#pragma unroll
        for (int mt = 0; mt < 4; mt++) {
            const int row = crow0 + wm * 64 + mt * 16 + lr;
#pragma unroll
            for (int nt = 0; nt < 8; nt++) {
                const int col = ccol0 + wn * 64 + nt * 8 + 2 * lc;
                *(uint32_t*)(C + (size_t)row * Nc + col)       = packh2(acc[mt][nt][0], acc[mt][nt][1]);
                *(uint32_t*)(C + (size_t)(row + 8) * Nc + col) = packh2(acc[mt][nt][2], acc[mt][nt][3]);
            }
        }
    }
}

// ---------------------------------------------------------------------------
// Plain GEMM for the output projection (fp32 out).
// ---------------------------------------------------------------------------
__global__ __launch_bounds__(128, 2) void gemm_wo(
    const __half* __restrict__ A, const __half* __restrict__ Bt, float* __restrict__ C,
    int M, int N, int K)
{
    extern __shared__ __half smh[];
    const uint32_t smbA = smem_u32(smh);
    const uint32_t smbB = smbA + 4 * STGH * 2;

    const int tid  = threadIdx.x;
    const int lane = tid & 31;
    const int warp = tid >> 5;
    const int wm = warp & 1;
    const int wn = warp >> 1;
    const int lr = lane >> 2;
    const int lc = lane & 3;
    const int crow0 = blockIdx.y * 128;
    const int ccol0 = blockIdx.x * 128;

    const int ldrow = tid >> 2;
    const int ldc   = tid & 3;

    float acc[4][8][4];
#pragma unroll
    for (int mt = 0; mt < 4; mt++)
#pragma unroll
        for (int nt = 0; nt < 8; nt++)
#pragma unroll
            for (int i = 0; i < 4; i++) acc[mt][nt][i] = 0.f;

    const int aRowBase = wm * 64 + (lane & 15);
    const int aKoff    = (lane >> 4) * 8;
    const int bRowBase = wn * 64 + (lane & 7) + ((lane >> 4) & 1) * 8;
    const int bKoff    = ((lane >> 3) & 1) * 8;

    const int T = K >> 5;
    GEMM_MAIN(T)

#pragma unroll
    for (int mt = 0; mt < 4; mt++) {
        const int row = crow0 + wm * 64 + mt * 16 + lr;
#pragma unroll
        for (int nt = 0; nt < 8; nt++) {
            const int col = ccol0 + wn * 64 + nt * 8 + 2 * lc;
            *(float2*)(C + (size_t)row * N + col)       = make_float2(acc[mt][nt][0], acc[mt][nt][1]);
            *(float2*)(C + (size_t)(row + 8) * N + col) = make_float2(acc[mt][nt][2], acc[mt][nt][3]);
        }
    }
}

// ---------------------------------------------------------------------------
// prep kernels
// ---------------------------------------------------------------------------
__global__ void round_half(const float* __restrict__ src, __half* __restrict__ dst, int n8) {
    int i = blockIdx.x * blockDim.x + threadIdx.x;
    if (i < n8) {
        float4 v0 = ((const float4*)src)[2 * i];
        float4 v1 = ((const float4*)src)[2 * i + 1];
        uint4 o;
        o.x = packh2(v0.x, v0.y); o.y = packh2(v0.z, v0.w);
        o.z = packh2(v1.x, v1.y); o.w = packh2(v1.z, v1.w);
        ((uint4*)dst)[i] = o;
    }
}
__global__ void transpose_half(const float* __restrict__ W, __half* __restrict__ Wt,
                               int K, int N) {
    __shared__ float t[32][33];
    const int n0 = blockIdx.x * 32, k0 = blockIdx.y * 32;
    const int x = threadIdx.x, y = threadIdx.y;
#pragma unroll
    for (int j = 0; j < 32; j += 8)
        t[y + j][x] = W[(size_t)(k0 + y + j) * N + n0 + x];
    __syncthreads();
#pragma unroll
    for (int j = 0; j < 32; j += 8)
        Wt[(size_t)(n0 + y + j) * K + k0 + x] = __float2half_rn(t[x][y + j]);
}
__global__ void transpose_half_perm(const float* __restrict__ W, __half* __restrict__ Wt,
                                    int K, int N) {
    __shared__ float t[32][33];
    const int n0 = blockIdx.x * 32, k0 = blockIdx.y * 32;
    const int x = threadIdx.x, y = threadIdx.y;
#pragma unroll
    for (int j = 0; j < 32; j += 8)
        t[y + j][x] = W[(size_t)(k0 + y + j) * N + n0 + x];
    __syncthreads();
#pragma unroll
    for (int j = 0; j < 32; j += 8) {
        const int n = n0 + y + j;
        const int d = n & 127;
        const int p = (d < 64) ? (2 * d) : (2 * (d - 64) + 1);
        const int npr = (n & ~127) | p;
        Wt[(size_t)npr * K + k0 + x] = __float2half_rn(t[x][y + j]);
    }
}

// ---------------------------------------------------------------------------
// Flash-style fp16 block-sparse attention. One CTA per (qblock, head, batch).
// 128 threads / 4 warps; each warp owns 16 rows x all 512 key-cols.
// Scores live in registers (S C-frag == P A-frag layout); online softmax;
// K/V double-buffered cp.async. smem: Qs + 2xK + 2xV (pitch 136) = 85KB.
// ---------------------------------------------------------------------------
#define AP    136                       // half pitch (272B, conflict-free)
#define ATILE (64 * AP)                 // halves per tile
#define SQ_H  0
#define SK_H  ATILE                     // [2][ATILE]
#define SV_H  (SK_H + 2 * ATILE)
#define ATTN2_SMEM_BYTES ((SV_H + 2 * ATILE) * 2)   // 87040 B

__global__ __launch_bounds__(128, 2) void attn_flash(
    const __half* __restrict__ Q, const __half* __restrict__ K, const __half* __restrict__ V,
    const float* __restrict__ mask, __half* __restrict__ AO)
{
    extern __shared__ __half smA[];
    const uint32_t Qaddr = smem_u32(smA + SQ_H);
    const uint32_t Kaddr = smem_u32(smA + SK_H);
    const uint32_t Vaddr = smem_u32(smA + SV_H);

    const int qb = blockIdx.x;
    const int h  = blockIdx.y;
    const int b  = blockIdx.z;
    const int kvh = h >> 2;
    const int tid = threadIdx.x;
    const int lane = tid & 31;
    const int warp = tid >> 5;       // 0..3
    const int lr = lane >> 2;
    const int lc = lane & 3;
    const int wr = warp * 16;        // warp's row base (block-local)

    // --- key-block table ---
    int kblk[8]; bool kvalid[8];
#pragma unroll
    for (int w = 0; w < 4; w++) {
        int jb = qb - 3 + w;
        kblk[w] = jb < 0 ? 0 : jb;
        kvalid[w] = (jb >= 0);
    }
    {
        int start = qb - 32; if (start < 0) start = 0;
        int cnt = (qb > start) ? ((qb - start + 3) >> 2) : 0;
        int first = (cnt > 4) ? (cnt - 4) : 0;
        int sz = (cnt < 4) ? cnt : 4;
        int s0 = 4 - sz;
#pragma unroll
        for (int g = 0; g < 4; g++) {
            if (g < s0) { kblk[4 + g] = 0; kvalid[4 + g] = false; }
            else        { kblk[4 + g] = start + 4 * (first + g - s0); kvalid[4 + g] = true; }
        }
    }

    const __half* Qsrc  = Q + (size_t)(b * 4096 + qb * 64) * 2048 + h * 128;
    const __half* Kbase = K + (size_t)b * 4096 * 512 + kvh * 128;
    const __half* Vbase = V + (size_t)b * 4096 * 512 + kvh * 128;

#define AKV_ISSUE(stage, blk)                                                          \
    do {                                                                               \
        const __half* ksrc = Kbase + (size_t)(blk) * 64 * 512;                         \
        const __half* vsrc = Vbase + (size_t)(blk) * 64 * 512;                         \
        _Pragma("unroll")                                                              \
        for (int it = 0; it < 8; it++) {                                               \
            const int f = tid + it * 128;                                              \
            const int row = f >> 4, c8 = f & 15;                                       \
            const uint32_t so = (stage) * (ATILE * 2) + (row * AP + c8 * 8) * 2;       \
            CP_ASYNC16(Kaddr + so, ksrc + (size_t)row * 512 + c8 * 8);                 \
            CP_ASYNC16(Vaddr + so, vsrc + (size_t)row * 512 + c8 * 8);                 \
        }                                                                              \
    } while (0)

    // prologue: Q + slot0 K/V in one group
#pragma unroll
    for (int it = 0; it < 8; it++) {
        const int f = tid + it * 128;
        const int row = f >> 4, c8 = f & 15;
        CP_ASYNC16(Qaddr + (row * AP + c8 * 8) * 2, Qsrc + (size_t)row * 2048 + c8 * 8);
    }
    AKV_ISSUE(0, kblk[0]);
    CP_COMMIT();
    CP_WAIT0();
    __syncthreads();

    // preload Q fragments (16 rows x 128 k per warp)
    uint32_t qf[8][4];
    const int aRow  = wr + (lane & 15);
    const int aKoff = (lane >> 4) * 8;
#pragma unroll
    for (int kk = 0; kk < 8; kk++)
        ldsm4(qf[kk], Qaddr + (aRow * AP + kk * 16 + aKoff) * 2);

    float o[16][4];
#pragma unroll
    for (int j = 0; j < 16; j++)
#pragma unroll
        for (int i = 0; i < 4; i++) o[j][i] = 0.f;
    float m_lo = -1e30f, m_hi = -1e30f, l_lo = 0.f, l_hi = 0.f;

    const int bRow  = (lane & 7) + ((lane >> 4) & 1) * 8;
    const int bKoff = ((lane >> 3) & 1) * 8;
    const int vKrow = (lane & 7) + ((lane >> 3) & 1) * 8;
    const int vDoff = ((lane >> 4) & 1) * 8;
    const int row_lo = wr + lr;

    for (int s = 0; s < 8; s++) {
        if (s < 7) { AKV_ISSUE((s + 1) & 1, kblk[s + 1]); CP_COMMIT(); }

        if (kvalid[s]) {
            const uint32_t Kst = Kaddr + (s & 1) * (ATILE * 2);
            const uint32_t Vst = Vaddr + (s & 1) * (ATILE * 2);

            // QK^T: 16 x 64 in registers
            float sc[8][4];
#pragma unroll
            for (int nt = 0; nt < 8; nt++)
#pragma unroll
                for (int i = 0; i < 4; i++) sc[nt][i] = 0.f;
#pragma unroll
            for (int kk = 0; kk < 8; kk++) {
                uint32_t br[4][4];
#pragma unroll
                for (int g = 0; g < 4; g++)
                    ldsm4(br[g], Kst + ((g * 16 + bRow) * AP + kk * 16 + bKoff) * 2);
#pragma unroll
                for (int nt = 0; nt < 8; nt++)
                    mma_f16(sc[nt], qf[kk], br[nt >> 1][(nt & 1) * 2], br[nt >> 1][(nt & 1) * 2 + 1]);
            }

            // scale + mask + causal (in registers)
            const float* mrow = mask + (size_t)b * 4096 + kblk[s] * 64;
            const bool cz = (s == 3);
#pragma unroll
            for (int nt = 0; nt < 8; nt++) {
                const int c0 = nt * 8 + 2 * lc;
                const float mv0 = (1.0f - __ldg(mrow + c0)) * NEGV;
                const float mv1 = (1.0f - __ldg(mrow + c0 + 1)) * NEGV;
                sc[nt][0] = sc[nt][0] * SCALEV + mv0;
                sc[nt][1] = sc[nt][1] * SCALEV + mv1;
                sc[nt][2] = sc[nt][2] * SCALEV + mv0;
                sc[nt][3] = sc[nt][3] * SCALEV + mv1;
                if (cz) {
                    if (c0     > row_lo)     sc[nt][0] += NEGV;
                    if (c0 + 1 > row_lo)     sc[nt][1] += NEGV;
                    if (c0     > row_lo + 8) sc[nt][2] += NEGV;
                    if (c0 + 1 > row_lo + 8) sc[nt][3] += NEGV;
                }
            }

            // online softmax (warp-local; lanes with same lr differ only in lc)
            float tm_lo = -1e30f, tm_hi = -1e30f;
#pragma unroll
            for (int nt = 0; nt < 8; nt++) {
                tm_lo = fmaxf(tm_lo, fmaxf(sc[nt][0], sc[nt][1]));
                tm_hi = fmaxf(tm_hi, fmaxf(sc[nt][2], sc[nt][3]));
            }
            tm_lo = fmaxf(tm_lo, __shfl_xor_sync(0xffffffffu, tm_lo, 1));
            tm_lo = fmaxf(tm_lo, __shfl_xor_sync(0xffffffffu, tm_lo, 2));
            tm_hi = fmaxf(tm_hi, __shfl_xor_sync(0xffffffffu, tm_hi, 1));
            tm_hi = fmaxf(tm_hi, __shfl_xor_sync(0xffffffffu, tm_hi, 2));

            const float mn_lo = fmaxf(m_lo, tm_lo);
            const float mn_hi = fmaxf(m_hi, tm_hi);
            const float r_lo = __expf(m_lo - mn_lo);
            const float r_hi = __expf(m_hi - mn_hi);
            m_lo = mn_lo; m_hi = mn_hi;

            float sl = 0.f, sh = 0.f;
#pragma unroll
            for (int nt = 0; nt < 8; nt++) {
                sc[nt][0] = __expf(sc[nt][0] - mn_lo);
                sc[nt][1] = __expf(sc[nt][1] - mn_lo);
                sc[nt][2] = __expf(sc[nt][2] - mn_hi);
                sc[nt][3] = __expf(sc[nt][3] - mn_hi);
                sl += sc[nt][0] + sc[nt][1];
                sh += sc[nt][2] + sc[nt][3];
            }
            l_lo = l_lo * r_lo + sl;
            l_hi = l_hi * r_hi + sh;
#pragma unroll
            for (int j = 0; j < 16; j++) {
                o[j][0] *= r_lo; o[j][1] *= r_lo;
                o[j][2] *= r_hi; o[j][3] *= r_hi;
            }

            // PV: P A-frags repacked directly from the S C-frags
#pragma unroll
            for (int t = 0; t < 4; t++) {
                uint32_t a[4] = {
                    packh2(sc[2 * t][0],     sc[2 * t][1]),
                    packh2(sc[2 * t][2],     sc[2 * t][3]),
                    packh2(sc[2 * t + 1][0], sc[2 * t + 1][1]),
                    packh2(sc[2 * t + 1][2], sc[2 * t + 1][3])
                };
#pragma unroll
                for (int dg = 0; dg < 8; dg++) {
                    uint32_t bv[4];
                    ldsm4t(bv, Vst + ((t * 16 + vKrow) * AP + dg * 16 + vDoff) * 2);
                    mma_f16(o[2 * dg],     a, bv[0], bv[1]);
                    mma_f16(o[2 * dg + 1], a, bv[2], bv[3]);
                }
            }
        }

        if (s < 7) { CP_WAIT0(); __syncthreads(); }
    }

    // finalize: reduce l over the lc quad, normalize, write
    l_lo += __shfl_xor_sync(0xffffffffu, l_lo, 1);
    l_lo += __shfl_xor_sync(0xffffffffu, l_lo, 2);
    l_hi += __shfl_xor_sync(0xffffffffu, l_hi, 1);
    l_hi += __shfl_xor_sync(0xffffffffu, l_hi, 2);
    const float il = 1.0f / l_lo;
    const float ih = 1.0f / l_hi;

    __half* aop = AO + (size_t)(b * 4096 + qb * 64 + wr) * 2048 + h * 128;
#pragma unroll
    for (int j = 0; j < 16; j++) {
        const int col = j * 8 + 2 * lc;
        *(uint32_t*)(aop + (size_t)lr * 2048 + col)       = packh2(o[j][0] * il, o[j][1] * il);
        *(uint32_t*)(aop + (size_t)(lr + 8) * 2048 + col) = packh2(o[j][2] * ih, o[j][3] * ih);
    }
}

// ---------------------------------------------------------------------------
extern "C" void kernel_launch(void* const* d_in, const int* in_sizes, int n_in,
                              void* d_out, int out_size)
{
    const float* hidden = (const float*)d_in[0];
    const float* cosp   = (const float*)d_in[1];
    const float* sinp   = (const float*)d_in[2];
    const float* maskp  = (const float*)d_in[3];
    const float* Wq     = (const float*)d_in[4];
    const float* Wk     = (const float*)d_in[5];
    const float* Wv     = (const float*)d_in[6];
    const float* Wo     = (const float*)d_in[7];
    float* out = (float*)d_out;

    __half *Qh, *Kh, *Vh, *AOh, *Xh, *WqT, *WkT, *WvT, *WoT;
    cudaGetSymbolAddress((void**)&Qh, g_Qh);
    cudaGetSymbolAddress((void**)&Kh, g_Kh);
    cudaGetSymbolAddress((void**)&Vh, g_Vh);
    cudaGetSymbolAddress((void**)&AOh, g_AOh);
    cudaGetSymbolAddress((void**)&Xh, g_Xh);
    cudaGetSymbolAddress((void**)&WqT, g_WqT);
    cudaGetSymbolAddress((void**)&WkT, g_WkT);
    cudaGetSymbolAddress((void**)&WvT, g_WvT);
    cudaGetSymbolAddress((void**)&WoT, g_WoT);

    cudaFuncSetAttribute(attn_flash, cudaFuncAttributeMaxDynamicSharedMemorySize,
                         ATTN2_SMEM_BYTES);
    cudaFuncSetAttribute(gemm_qkv, cudaFuncAttributeMaxDynamicSharedMemorySize,
                         GSMH_BYTES);
    cudaFuncSetAttribute(gemm_wo, cudaFuncAttributeMaxDynamicSharedMemorySize,
                         GSMH_BYTES);

    // prep: hidden -> half; weights -> transposed half (Wq/Wk rope-pair perm)
    const int n8 = 2 * 4096 * 2048 / 8;
    round_half<<<(n8 + 255) / 256, 256>>>(hidden, Xh, n8);
    transpose_half_perm<<<dim3(2048 / 32, 2048 / 32), dim3(32, 8)>>>(Wq, WqT, 2048, 2048);
    transpose_half_perm<<<dim3(512 / 32, 2048 / 32), dim3(32, 8)>>>(Wk, WkT, 2048, 512);
    transpose_half<<<dim3(512 / 32, 2048 / 32), dim3(32, 8)>>>(Wv, WvT, 2048, 512);
    transpose_half<<<dim3(2048 / 32, 2048 / 32), dim3(32, 8)>>>(Wo, WoT, 2048, 2048);

    // fused QKV projections + RoPE
    gemm_qkv<<<dim3(24, 64), 128, GSMH_BYTES>>>(Xh, WqT, WkT, WvT, Qh, Kh, Vh, cosp, sinp);

    // flash-style fp16 block-sparse attention
    attn_flash<<<dim3(64, 16, 2), 128, ATTN2_SMEM_BYTES>>>(Qh, Kh, Vh, maskp, AOh);

    // output projection
    gemm_wo<<<dim3(16, 64), 128, GSMH_BYTES>>>(AOh, WoT, out, 8192, 2048, 2048);
}